// round 1
// baseline (speedup 1.0000x reference)
#include <cuda_runtime.h>
#include <math.h>

// Problem constants
#define TOK   8192      // B*S
#define CDIM  768
#define FDIM  3072
#define BB    8
#define SS    1024
#define HH    12
#define DD    64

// ---------------------------------------------------------------------------
// Scratch (device globals -- no allocation allowed)
// ---------------------------------------------------------------------------
__device__ float g_xn [TOK * CDIM];   // LN1 output
__device__ float g_q  [TOK * CDIM];
__device__ float g_k  [TOK * CDIM];
__device__ float g_v  [TOK * CDIM];
__device__ float g_ctx[TOK * CDIM];   // attention context
__device__ float g_hid[TOK * CDIM];   // after O-proj + lam1 + residual
__device__ float g_y2 [TOK * CDIM];   // LN2 output
__device__ float g_fc1[TOK * FDIM];   // GELU(fc1) output

// ---------------------------------------------------------------------------
// LayerNorm: one block per token row (C = 768), 256 threads
// ---------------------------------------------------------------------------
__global__ __launch_bounds__(256) void ln_kernel(
    const float* __restrict__ x, const float* __restrict__ w,
    const float* __restrict__ b, float* __restrict__ out)
{
    int row = blockIdx.x;
    const float* xr = x + (size_t)row * CDIM;
    float s = 0.f, s2 = 0.f;
    for (int c = threadIdx.x; c < CDIM; c += 256) {
        float v = xr[c];
        s += v; s2 += v * v;
    }
    __shared__ float sh[16];
    #pragma unroll
    for (int o = 16; o > 0; o >>= 1) {
        s  += __shfl_down_sync(0xffffffffu, s,  o);
        s2 += __shfl_down_sync(0xffffffffu, s2, o);
    }
    int warp = threadIdx.x >> 5, lane = threadIdx.x & 31;
    if (lane == 0) { sh[warp] = s; sh[warp + 8] = s2; }
    __syncthreads();
    if (threadIdx.x == 0) {
        float a = 0.f, c2 = 0.f;
        #pragma unroll
        for (int i = 0; i < 8; i++) { a += sh[i]; c2 += sh[i + 8]; }
        sh[0] = a  * (1.0f / CDIM);
        sh[8] = c2 * (1.0f / CDIM);
    }
    __syncthreads();
    float mu  = sh[0];
    float var = sh[8] - mu * mu;
    float inv = rsqrtf(var + 1e-6f);
    float* orow = out + (size_t)row * CDIM;
    for (int c = threadIdx.x; c < CDIM; c += 256)
        orow[c] = (xr[c] - mu) * inv * w[c] + b[c];
}

// ---------------------------------------------------------------------------
// SGEMM: C[M,N] = A[M,K] @ B[K,N] (+ epilogue)
// 128x128 blocktile, BK=8, 256 threads, 8x8 microtile per thread.
// Requires M%128==0, N%128==0, K%8==0 (true for all shapes here).
// EPI: 0 = +bias
//      1 = (+bias)*lam + res     (O-proj w/ lam1+shortcut; FC2 w/ lam2+hidden)
//      2 = gelu_exact(+bias)     (FC1)
// ---------------------------------------------------------------------------
template<int EPI>
__global__ __launch_bounds__(256) void sgemm(
    const float* __restrict__ A, const float* __restrict__ B,
    const float* __restrict__ bias, float* __restrict__ Cout,
    int M, int N, int K,
    const float* __restrict__ lam, const float* __restrict__ res)
{
    __shared__ float As[8][128];
    __shared__ float Bs[8][128];

    const int tid = threadIdx.x;
    const int tx  = tid & 15;          // 0..15 -> N direction
    const int ty  = tid >> 4;          // 0..15 -> M direction
    const int tx8 = tx * 8, ty8 = ty * 8;
    const int m0 = blockIdx.y * 128;
    const int n0 = blockIdx.x * 128;

    // loader coords
    const int arow = tid >> 1;         // 0..127
    const int acol = (tid & 1) * 4;    // 0 or 4
    const int brow = tid >> 5;         // 0..7
    const int bcol = (tid & 31) * 4;   // 0..124

    float acc[8][8];
    #pragma unroll
    for (int i = 0; i < 8; i++)
        #pragma unroll
        for (int j = 0; j < 8; j++) acc[i][j] = 0.f;

    for (int k0 = 0; k0 < K; k0 += 8) {
        float4 av = *(const float4*)(A + (size_t)(m0 + arow) * K + k0 + acol);
        float4 bv = *(const float4*)(B + (size_t)(k0 + brow) * N + n0 + bcol);
        As[acol + 0][arow] = av.x;
        As[acol + 1][arow] = av.y;
        As[acol + 2][arow] = av.z;
        As[acol + 3][arow] = av.w;
        *(float4*)(&Bs[brow][bcol]) = bv;
        __syncthreads();

        #pragma unroll
        for (int kk = 0; kk < 8; kk++) {
            float ra[8], rb[8];
            float4 a0 = *(const float4*)(&As[kk][ty8]);
            float4 a1 = *(const float4*)(&As[kk][ty8 + 4]);
            float4 b0 = *(const float4*)(&Bs[kk][tx8]);
            float4 b1 = *(const float4*)(&Bs[kk][tx8 + 4]);
            ra[0]=a0.x; ra[1]=a0.y; ra[2]=a0.z; ra[3]=a0.w;
            ra[4]=a1.x; ra[5]=a1.y; ra[6]=a1.z; ra[7]=a1.w;
            rb[0]=b0.x; rb[1]=b0.y; rb[2]=b0.z; rb[3]=b0.w;
            rb[4]=b1.x; rb[5]=b1.y; rb[6]=b1.z; rb[7]=b1.w;
            #pragma unroll
            for (int i = 0; i < 8; i++)
                #pragma unroll
                for (int j = 0; j < 8; j++)
                    acc[i][j] = fmaf(ra[i], rb[j], acc[i][j]);
        }
        __syncthreads();
    }

    #pragma unroll
    for (int i = 0; i < 8; i++) {
        int r = m0 + ty8 + i;
        size_t rowoff = (size_t)r * N;
        #pragma unroll
        for (int j = 0; j < 8; j++) {
            int c = n0 + tx8 + j;
            float v = acc[i][j] + bias[c];
            if (EPI == 1) {
                v = v * lam[c] + res[rowoff + c];
            } else if (EPI == 2) {
                v = 0.5f * v * (1.0f + erff(v * 0.70710678118654752f));
            }
            Cout[rowoff + c] = v;
        }
    }
}

// ---------------------------------------------------------------------------
// Flash attention (fp32, online softmax).
// Grid: (S/64, H, B). Block: 256 threads. BM = BN = 64, D = 64.
// q/k/v layouts: [tok, C] with head h occupying cols [h*64, h*64+64).
// ---------------------------------------------------------------------------
__global__ __launch_bounds__(256) void attn_kernel(
    const float* __restrict__ q, const float* __restrict__ k,
    const float* __restrict__ v, float* __restrict__ ctx)
{
    extern __shared__ float sm[];
    float* qs   = sm;                 // [64][65]
    float* ks   = qs + 64 * 65;       // [64][65]
    float* vs   = ks + 64 * 65;       // [64][65]  (row = key idx, col = d)
    float* ss   = vs + 64 * 65;       // [64][65]  scores / probs
    float* m_s  = ss + 64 * 65;       // [64]
    float* l_s  = m_s + 64;           // [64]
    float* al_s = l_s + 64;           // [64]

    const int tid = threadIdx.x;
    const int h   = blockIdx.y;
    const int b   = blockIdx.z;
    const int q0  = blockIdx.x * 64;
    const size_t base = (size_t)b * SS * CDIM + h * DD;

    // load Q tile [64 x 64]
    for (int i = tid; i < 64 * 16; i += 256) {
        int r = i >> 4, c4 = (i & 15) * 4;
        float4 t = *(const float4*)(q + base + (size_t)(q0 + r) * CDIM + c4);
        qs[r * 65 + c4 + 0] = t.x; qs[r * 65 + c4 + 1] = t.y;
        qs[r * 65 + c4 + 2] = t.z; qs[r * 65 + c4 + 3] = t.w;
    }
    if (tid < 64) { m_s[tid] = -1e30f; l_s[tid] = 0.f; }

    const int ty = tid >> 4, tx = tid & 15;
    const int r0 = ty * 4, c0 = tx * 4;
    float oacc[4][4];
    #pragma unroll
    for (int i = 0; i < 4; i++)
        #pragma unroll
        for (int j = 0; j < 4; j++) oacc[i][j] = 0.f;

    for (int j0 = 0; j0 < SS; j0 += 64) {
        __syncthreads();   // previous iter's vs/ss reads done
        for (int i = tid; i < 64 * 16; i += 256) {
            int r = i >> 4, c4 = (i & 15) * 4;
            float4 tk = *(const float4*)(k + base + (size_t)(j0 + r) * CDIM + c4);
            ks[r * 65 + c4 + 0] = tk.x; ks[r * 65 + c4 + 1] = tk.y;
            ks[r * 65 + c4 + 2] = tk.z; ks[r * 65 + c4 + 3] = tk.w;
            float4 tv = *(const float4*)(v + base + (size_t)(j0 + r) * CDIM + c4);
            vs[r * 65 + c4 + 0] = tv.x; vs[r * 65 + c4 + 1] = tv.y;
            vs[r * 65 + c4 + 2] = tv.z; vs[r * 65 + c4 + 3] = tv.w;
        }
        __syncthreads();

        // S = Q @ K^T  (4x4 microtile per thread)
        float sa[4][4];
        #pragma unroll
        for (int i = 0; i < 4; i++)
            #pragma unroll
            for (int j = 0; j < 4; j++) sa[i][j] = 0.f;

        #pragma unroll 8
        for (int kk = 0; kk < 64; kk++) {
            float ra[4], rb[4];
            #pragma unroll
            for (int i = 0; i < 4; i++) ra[i] = qs[(r0 + i) * 65 + kk];
            #pragma unroll
            for (int j = 0; j < 4; j++) rb[j] = ks[(c0 + j) * 65 + kk];
            #pragma unroll
            for (int i = 0; i < 4; i++)
                #pragma unroll
                for (int j = 0; j < 4; j++)
                    sa[i][j] = fmaf(ra[i], rb[j], sa[i][j]);
        }
        #pragma unroll
        for (int i = 0; i < 4; i++)
            #pragma unroll
            for (int j = 0; j < 4; j++)
                ss[(r0 + i) * 65 + c0 + j] = sa[i][j] * 0.125f;  // 1/sqrt(64)
        __syncthreads();

        // online softmax over this tile (one thread per row)
        if (tid < 64) {
            int r = tid;
            float mold = m_s[r];
            float tmax = -1e30f;
            #pragma unroll 8
            for (int c = 0; c < 64; c++) tmax = fmaxf(tmax, ss[r * 65 + c]);
            float mnew = fmaxf(mold, tmax);
            float a = __expf(mold - mnew);
            float sum = 0.f;
            #pragma unroll 8
            for (int c = 0; c < 64; c++) {
                float p = __expf(ss[r * 65 + c] - mnew);
                ss[r * 65 + c] = p;
                sum += p;
            }
            l_s[r]  = l_s[r] * a + sum;
            m_s[r]  = mnew;
            al_s[r] = a;
        }
        __syncthreads();

        // O = O*alpha + P @ V
        float ar[4];
        #pragma unroll
        for (int i = 0; i < 4; i++) ar[i] = al_s[r0 + i];
        #pragma unroll
        for (int i = 0; i < 4; i++)
            #pragma unroll
            for (int j = 0; j < 4; j++) oacc[i][j] *= ar[i];

        #pragma unroll 8
        for (int kk = 0; kk < 64; kk++) {
            float rp[4], rv[4];
            #pragma unroll
            for (int i = 0; i < 4; i++) rp[i] = ss[(r0 + i) * 65 + kk];
            #pragma unroll
            for (int j = 0; j < 4; j++) rv[j] = vs[kk * 65 + c0 + j];
            #pragma unroll
            for (int i = 0; i < 4; i++)
                #pragma unroll
                for (int j = 0; j < 4; j++)
                    oacc[i][j] = fmaf(rp[i], rv[j], oacc[i][j]);
        }
    }
    __syncthreads();

    float linv[4];
    #pragma unroll
    for (int i = 0; i < 4; i++) linv[i] = 1.0f / l_s[r0 + i];
    #pragma unroll
    for (int i = 0; i < 4; i++) {
        size_t off = base + (size_t)(q0 + r0 + i) * CDIM + c0;
        #pragma unroll
        for (int j = 0; j < 4; j++)
            ctx[off + j] = oacc[i][j] * linv[i];
    }
}

// ---------------------------------------------------------------------------
// Launch
// ---------------------------------------------------------------------------
extern "C" void kernel_launch(void* const* d_in, const int* in_sizes, int n_in,
                              void* d_out, int out_size)
{
    const float* hs    = (const float*)d_in[0];
    const float* ln1_w = (const float*)d_in[1];
    const float* ln1_b = (const float*)d_in[2];
    const float* q_w   = (const float*)d_in[3];
    const float* q_b   = (const float*)d_in[4];
    const float* k_w   = (const float*)d_in[5];
    const float* k_b   = (const float*)d_in[6];
    const float* v_w   = (const float*)d_in[7];
    const float* v_b   = (const float*)d_in[8];
    const float* o_w   = (const float*)d_in[9];
    const float* o_b   = (const float*)d_in[10];
    const float* lam1  = (const float*)d_in[11];
    const float* ln2_w = (const float*)d_in[12];
    const float* ln2_b = (const float*)d_in[13];
    const float* fc1_w = (const float*)d_in[14];
    const float* fc1_b = (const float*)d_in[15];
    const float* fc2_w = (const float*)d_in[16];
    const float* fc2_b = (const float*)d_in[17];
    const float* lam2  = (const float*)d_in[18];
    float* out = (float*)d_out;

    float *xn, *qb, *kb, *vb, *ctx, *hid, *y2, *fc1;
    cudaGetSymbolAddress((void**)&xn,  g_xn);
    cudaGetSymbolAddress((void**)&qb,  g_q);
    cudaGetSymbolAddress((void**)&kb,  g_k);
    cudaGetSymbolAddress((void**)&vb,  g_v);
    cudaGetSymbolAddress((void**)&ctx, g_ctx);
    cudaGetSymbolAddress((void**)&hid, g_hid);
    cudaGetSymbolAddress((void**)&y2,  g_y2);
    cudaGetSymbolAddress((void**)&fc1, g_fc1);

    // 1) LN1
    ln_kernel<<<TOK, 256>>>(hs, ln1_w, ln1_b, xn);

    // 2) QKV projections
    dim3 gC(CDIM / 128, TOK / 128);           // (6, 64)
    sgemm<0><<<gC, 256>>>(xn, q_w, q_b, qb, TOK, CDIM, CDIM, nullptr, nullptr);
    sgemm<0><<<gC, 256>>>(xn, k_w, k_b, kb, TOK, CDIM, CDIM, nullptr, nullptr);
    sgemm<0><<<gC, 256>>>(xn, v_w, v_b, vb, TOK, CDIM, CDIM, nullptr, nullptr);

    // 3) attention
    size_t shm = (4 * 64 * 65 + 3 * 64) * sizeof(float);   // 67328 B
    cudaFuncSetAttribute(attn_kernel, cudaFuncAttributeMaxDynamicSharedMemorySize,
                         (int)shm);
    attn_kernel<<<dim3(SS / 64, HH, BB), 256, shm>>>(qb, kb, vb, ctx);

    // 4) O projection + lam1 * . + shortcut
    sgemm<1><<<gC, 256>>>(ctx, o_w, o_b, hid, TOK, CDIM, CDIM, lam1, hs);

    // 5) LN2
    ln_kernel<<<TOK, 256>>>(hid, ln2_w, ln2_b, y2);

    // 6) FC1 + exact GELU
    dim3 gF(FDIM / 128, TOK / 128);           // (24, 64)
    sgemm<2><<<gF, 256>>>(y2, fc1_w, fc1_b, fc1, TOK, FDIM, CDIM, nullptr, nullptr);

    // 7) FC2 + lam2 * . + hidden
    sgemm<1><<<gC, 256>>>(fc1, fc2_w, fc2_b, out, TOK, CDIM, FDIM, lam2, hid);
}

// round 3
// speedup vs baseline: 1.2743x; 1.2743x over previous
#include <cuda_runtime.h>
#include <cuda_bf16.h>
#include <math.h>
#include <cstdint>

// Problem constants
#define TOK   8192      // B*S
#define CDIM  768
#define FDIM  3072
#define QKVC  2304      // 3*C
#define BB    8
#define SS    1024
#define HH    12
#define DD    64

// ===========================================================================
// Scratch (device globals -- no allocation allowed)
// ===========================================================================
__device__ float g_wqkvT[QKVC * CDIM];   // [N=2304][K=768]
__device__ float g_woT  [CDIM * CDIM];   // [768][768]
__device__ float g_wf1T [FDIM * CDIM];   // [3072][768]
__device__ float g_wf2T [CDIM * FDIM];   // [768][3072]
__device__ float g_qkvb [QKVC];
__device__ float g_xn  [TOK * CDIM];
__device__ float g_qkv [TOK * QKVC];
__device__ float g_ctx [TOK * CDIM];
__device__ float g_hid [TOK * CDIM];
__device__ float g_y2  [TOK * CDIM];
__device__ float g_h1  [TOK * FDIM];

// ===========================================================================
// Small PTX helpers (base ISA only -- no 'a'-gated features)
// ===========================================================================
__device__ __forceinline__ uint32_t smem_u32(const void* p) {
    uint32_t a;
    asm("{ .reg .u64 t; cvta.to.shared.u64 t, %1; cvt.u32.u64 %0, t; }"
        : "=r"(a) : "l"(p));
    return a;
}
__device__ __forceinline__ void cp_async16(uint32_t s, const void* g) {
    asm volatile("cp.async.cg.shared.global [%0], [%1], 16;" :: "r"(s), "l"(g));
}
#define CP_COMMIT() asm volatile("cp.async.commit_group;")
#define CP_WAIT1()  asm volatile("cp.async.wait_group 1;")
#define CP_WAIT0()  asm volatile("cp.async.wait_group 0;")

// D += A @ B  (m16n8k16, bf16 inputs, f32 accum)
__device__ __forceinline__ void mma_bf16(float* c, const uint32_t* a, const uint32_t* b) {
    asm volatile(
        "mma.sync.aligned.m16n8k16.row.col.f32.bf16.bf16.f32 "
        "{%0,%1,%2,%3}, {%4,%5,%6,%7}, {%8,%9}, {%0,%1,%2,%3};"
        : "+f"(c[0]), "+f"(c[1]), "+f"(c[2]), "+f"(c[3])
        : "r"(a[0]), "r"(a[1]), "r"(a[2]), "r"(a[3]), "r"(b[0]), "r"(b[1]));
}

// split fp32 pair -> (hi bf16x2, lo bf16x2); x0 -> low 16 bits (smaller k)
__device__ __forceinline__ void split2(float x0, float x1, uint32_t& hi, uint32_t& lo) {
    __nv_bfloat16 h0 = __float2bfloat16_rn(x0);
    __nv_bfloat16 h1 = __float2bfloat16_rn(x1);
    float r0 = x0 - __bfloat162float(h0);
    float r1 = x1 - __bfloat162float(h1);
    __nv_bfloat16 l0 = __float2bfloat16_rn(r0);
    __nv_bfloat16 l1 = __float2bfloat16_rn(r1);
    uint16_t uh0 = *(uint16_t*)&h0, uh1 = *(uint16_t*)&h1;
    uint16_t ul0 = *(uint16_t*)&l0, ul1 = *(uint16_t*)&l1;
    hi = (uint32_t)uh0 | ((uint32_t)uh1 << 16);
    lo = (uint32_t)ul0 | ((uint32_t)ul1 << 16);
}

// ===========================================================================
// Weight transpose: W[K,N] -> out[N,K] (fp32)
// ===========================================================================
__global__ __launch_bounds__(256) void wtrans(
    const float* __restrict__ W, int K, int N, float* __restrict__ out)
{
    __shared__ float t[32][33];
    const int n0 = blockIdx.x * 32, k0 = blockIdx.y * 32;
    const int tx = threadIdx.x, ty = threadIdx.y;   // (32, 8)
    #pragma unroll
    for (int i = 0; i < 32; i += 8)
        t[ty + i][tx] = W[(size_t)(k0 + ty + i) * N + n0 + tx];
    __syncthreads();
    #pragma unroll
    for (int i = 0; i < 32; i += 8)
        out[(size_t)(n0 + ty + i) * K + k0 + tx] = t[tx][ty + i];
}

__global__ void catbias(const float* __restrict__ qb, const float* __restrict__ kb,
                        const float* __restrict__ vb, float* __restrict__ out)
{
    int i = blockIdx.x * blockDim.x + threadIdx.x;
    if (i < CDIM)            out[i] = qb[i];
    else if (i < 2 * CDIM)   out[i] = kb[i - CDIM];
    else if (i < 3 * CDIM)   out[i] = vb[i - 2 * CDIM];
}

// ===========================================================================
// LayerNorm (fp32 out). One block per token row, 256 threads.
// ===========================================================================
__global__ __launch_bounds__(256) void ln_kernel(
    const float* __restrict__ x, const float* __restrict__ w,
    const float* __restrict__ b, float* __restrict__ out)
{
    int row = blockIdx.x;
    const float* xr = x + (size_t)row * CDIM;
    float s = 0.f, s2 = 0.f;
    for (int c = threadIdx.x; c < CDIM; c += 256) {
        float v = xr[c];
        s += v; s2 += v * v;
    }
    __shared__ float sh[16];
    #pragma unroll
    for (int o = 16; o > 0; o >>= 1) {
        s  += __shfl_down_sync(0xffffffffu, s,  o);
        s2 += __shfl_down_sync(0xffffffffu, s2, o);
    }
    int warp = threadIdx.x >> 5, lane = threadIdx.x & 31;
    if (lane == 0) { sh[warp] = s; sh[warp + 8] = s2; }
    __syncthreads();
    if (threadIdx.x == 0) {
        float a = 0.f, c2 = 0.f;
        #pragma unroll
        for (int i = 0; i < 8; i++) { a += sh[i]; c2 += sh[i + 8]; }
        sh[0] = a  * (1.0f / CDIM);
        sh[8] = c2 * (1.0f / CDIM);
    }
    __syncthreads();
    float mu  = sh[0];
    float var = sh[8] - mu * mu;
    float inv = rsqrtf(var + 1e-6f);
    float* orow = out + (size_t)row * CDIM;
    for (int c = threadIdx.x; c < CDIM; c += 256)
        orow[c] = (xr[c] - mu) * inv * w[c] + b[c];
}

// ===========================================================================
// bf16-split tensor GEMM: C[M,N] = A[M,K] @ B[N,K]^T (+ epilogue), fp32 I/O.
// 128x128 CTA tile, BK=32, cp.async double buffer, 256 threads (8 warps 2x4).
// Each warp: 64m x 32n via m16n8k16; 3 MMAs (hh, hl, lh) per tile pair.
// EPI 0: +bias ; EPI 1: (+bias)*lam + res ; EPI 2: gelu_exact(+bias)
// ===========================================================================
#define KSTRIDE 36                       // floats per smem row (pad 32->36)
#define TILE_F  (128 * KSTRIDE)          // floats per tile
#define GEMM_SMEM (4 * TILE_F * 4)       // bytes: A0,B0,A1,B1

template<int EPI>
__global__ __launch_bounds__(256) void mmagemm(
    const float* __restrict__ A, const float* __restrict__ B,
    const float* __restrict__ bias, float* __restrict__ C,
    int M, int N, int K,
    const float* __restrict__ lam, const float* __restrict__ res)
{
    extern __shared__ float sm[];
    float* bufA[2] = { sm,            sm + 2 * TILE_F };
    float* bufB[2] = { sm + TILE_F,   sm + 3 * TILE_F };

    const int tid  = threadIdx.x;
    const int wid  = tid >> 5;
    const int lane = tid & 31;
    const int wm   = wid & 1;            // 0..1 -> m offset
    const int wn   = wid >> 1;           // 0..3 -> n offset
    const int m0   = blockIdx.y * 128;
    const int n0   = blockIdx.x * 128;

    auto load_tile = [&](const float* __restrict__ G, int row0, int k0, float* dst) {
        #pragma unroll
        for (int i = 0; i < 4; i++) {
            int idx = tid + (i << 8);            // 0..1023
            int r   = idx >> 3;
            int ch  = (idx & 7) << 2;            // 0,4,...,28
            cp_async16(smem_u32(dst + r * KSTRIDE + ch),
                       G + (size_t)(row0 + r) * K + k0 + ch);
        }
    };

    float acc[4][4][4];
    #pragma unroll
    for (int t = 0; t < 4; t++)
        #pragma unroll
        for (int u = 0; u < 4; u++)
            #pragma unroll
            for (int e = 0; e < 4; e++) acc[t][u][e] = 0.f;

    const int nch = K >> 5;   // BK = 32

    load_tile(A, m0, 0, bufA[0]);
    load_tile(B, n0, 0, bufB[0]);
    CP_COMMIT();
    load_tile(A, m0, 32, bufA[1]);
    load_tile(B, n0, 32, bufB[1]);
    CP_COMMIT();

    for (int it = 0; it < nch; ++it) {
        const int p = it & 1;
        if (it + 1 < nch) { CP_WAIT1(); } else { CP_WAIT0(); }
        __syncthreads();

        const float* sA = bufA[p];
        const float* sB = bufB[p];

        #pragma unroll
        for (int ks = 0; ks < 2; ks++) {
            const int kof = ks * 16 + (lane & 3) * 2;
            uint32_t ahi[4][4], alo[4][4], bhi[4][2], blo[4][2];
            #pragma unroll
            for (int t = 0; t < 4; t++) {
                int r = wm * 64 + t * 16 + (lane >> 2);
                const float* p00 = sA + r * KSTRIDE + kof;
                float2 v0 = *(const float2*)(p00);
                float2 v1 = *(const float2*)(p00 + 8 * KSTRIDE);
                float2 v2 = *(const float2*)(p00 + 8);
                float2 v3 = *(const float2*)(p00 + 8 * KSTRIDE + 8);
                split2(v0.x, v0.y, ahi[t][0], alo[t][0]);
                split2(v1.x, v1.y, ahi[t][1], alo[t][1]);
                split2(v2.x, v2.y, ahi[t][2], alo[t][2]);
                split2(v3.x, v3.y, ahi[t][3], alo[t][3]);
            }
            #pragma unroll
            for (int u = 0; u < 4; u++) {
                int n = wn * 32 + u * 8 + (lane >> 2);
                const float* q0 = sB + n * KSTRIDE + kof;
                float2 w0 = *(const float2*)(q0);
                float2 w1 = *(const float2*)(q0 + 8);
                split2(w0.x, w0.y, bhi[u][0], blo[u][0]);
                split2(w1.x, w1.y, bhi[u][1], blo[u][1]);
            }
            #pragma unroll
            for (int t = 0; t < 4; t++)
                #pragma unroll
                for (int u = 0; u < 4; u++) {
                    mma_bf16(acc[t][u], ahi[t], bhi[u]);
                    mma_bf16(acc[t][u], ahi[t], blo[u]);
                    mma_bf16(acc[t][u], alo[t], bhi[u]);
                }
        }
        __syncthreads();
        if (it + 2 < nch) {
            load_tile(A, m0, (it + 2) << 5, bufA[p]);
            load_tile(B, n0, (it + 2) << 5, bufB[p]);
            CP_COMMIT();
        }
    }

    // Epilogue
    #pragma unroll
    for (int t = 0; t < 4; t++) {
        int r = m0 + wm * 64 + t * 16 + (lane >> 2);
        #pragma unroll
        for (int u = 0; u < 4; u++) {
            int c = n0 + wn * 32 + u * 8 + (lane & 3) * 2;
            #pragma unroll
            for (int half = 0; half < 2; half++) {
                int rr = r + half * 8;
                size_t ro = (size_t)rr * N;
                #pragma unroll
                for (int e = 0; e < 2; e++) {
                    int cc = c + e;
                    float v = acc[t][u][half * 2 + e] + bias[cc];
                    if (EPI == 1) {
                        v = v * lam[cc] + res[ro + cc];
                    } else if (EPI == 2) {
                        v = 0.5f * v * (1.0f + erff(v * 0.70710678118654752f));
                    }
                    C[ro + cc] = v;
                }
            }
        }
    }
}

// ===========================================================================
// Flash attention (fp32, online softmax). Reads fused qkv [tok, 2304],
// writes ctx fp32 [tok, 768]. Grid: (S/64, H, B). 256 threads.
// ===========================================================================
__global__ __launch_bounds__(256) void attn_kernel(
    const float* __restrict__ qkv, float* __restrict__ ctx)
{
    extern __shared__ float smf[];
    float* qs   = smf;                 // [64][65]
    float* ks   = qs + 64 * 65;
    float* vs   = ks + 64 * 65;
    float* ss   = vs + 64 * 65;
    float* m_s  = ss + 64 * 65;
    float* l_s  = m_s + 64;
    float* al_s = l_s + 64;

    const int tid = threadIdx.x;
    const int h   = blockIdx.y;
    const int b   = blockIdx.z;
    const int q0  = blockIdx.x * 64;
    const size_t base = (size_t)b * SS * QKVC + h * DD;

    for (int i = tid; i < 64 * 16; i += 256) {
        int r = i >> 4, c4 = (i & 15) * 4;
        float4 t = *(const float4*)(qkv + base + (size_t)(q0 + r) * QKVC + c4);
        qs[r * 65 + c4 + 0] = t.x; qs[r * 65 + c4 + 1] = t.y;
        qs[r * 65 + c4 + 2] = t.z; qs[r * 65 + c4 + 3] = t.w;
    }
    if (tid < 64) { m_s[tid] = -1e30f; l_s[tid] = 0.f; }

    const int ty = tid >> 4, tx = tid & 15;
    const int r0 = ty * 4, c0 = tx * 4;
    float oacc[4][4];
    #pragma unroll
    for (int i = 0; i < 4; i++)
        #pragma unroll
        for (int j = 0; j < 4; j++) oacc[i][j] = 0.f;

    for (int j0 = 0; j0 < SS; j0 += 64) {
        __syncthreads();
        for (int i = tid; i < 64 * 16; i += 256) {
            int r = i >> 4, c4 = (i & 15) * 4;
            float4 tk = *(const float4*)(qkv + base + CDIM + (size_t)(j0 + r) * QKVC + c4);
            ks[r * 65 + c4 + 0] = tk.x; ks[r * 65 + c4 + 1] = tk.y;
            ks[r * 65 + c4 + 2] = tk.z; ks[r * 65 + c4 + 3] = tk.w;
            float4 tv = *(const float4*)(qkv + base + 2 * CDIM + (size_t)(j0 + r) * QKVC + c4);
            vs[r * 65 + c4 + 0] = tv.x; vs[r * 65 + c4 + 1] = tv.y;
            vs[r * 65 + c4 + 2] = tv.z; vs[r * 65 + c4 + 3] = tv.w;
        }
        __syncthreads();

        float sa[4][4];
        #pragma unroll
        for (int i = 0; i < 4; i++)
            #pragma unroll
            for (int j = 0; j < 4; j++) sa[i][j] = 0.f;

        #pragma unroll 8
        for (int kk = 0; kk < 64; kk++) {
            float ra[4], rb[4];
            #pragma unroll
            for (int i = 0; i < 4; i++) ra[i] = qs[(r0 + i) * 65 + kk];
            #pragma unroll
            for (int j = 0; j < 4; j++) rb[j] = ks[(c0 + j) * 65 + kk];
            #pragma unroll
            for (int i = 0; i < 4; i++)
                #pragma unroll
                for (int j = 0; j < 4; j++)
                    sa[i][j] = fmaf(ra[i], rb[j], sa[i][j]);
        }
        #pragma unroll
        for (int i = 0; i < 4; i++)
            #pragma unroll
            for (int j = 0; j < 4; j++)
                ss[(r0 + i) * 65 + c0 + j] = sa[i][j] * 0.125f;
        __syncthreads();

        if (tid < 64) {
            int r = tid;
            float mold = m_s[r];
            float tmax = -1e30f;
            #pragma unroll 8
            for (int c = 0; c < 64; c++) tmax = fmaxf(tmax, ss[r * 65 + c]);
            float mnew = fmaxf(mold, tmax);
            float a = __expf(mold - mnew);
            float sum = 0.f;
            #pragma unroll 8
            for (int c = 0; c < 64; c++) {
                float pcur = __expf(ss[r * 65 + c] - mnew);
                ss[r * 65 + c] = pcur;
                sum += pcur;
            }
            l_s[r]  = l_s[r] * a + sum;
            m_s[r]  = mnew;
            al_s[r] = a;
        }
        __syncthreads();

        float ar[4];
        #pragma unroll
        for (int i = 0; i < 4; i++) ar[i] = al_s[r0 + i];
        #pragma unroll
        for (int i = 0; i < 4; i++)
            #pragma unroll
            for (int j = 0; j < 4; j++) oacc[i][j] *= ar[i];

        #pragma unroll 8
        for (int kk = 0; kk < 64; kk++) {
            float rp[4], rv[4];
            #pragma unroll
            for (int i = 0; i < 4; i++) rp[i] = ss[(r0 + i) * 65 + kk];
            #pragma unroll
            for (int j = 0; j < 4; j++) rv[j] = vs[kk * 65 + c0 + j];
            #pragma unroll
            for (int i = 0; i < 4; i++)
                #pragma unroll
                for (int j = 0; j < 4; j++)
                    oacc[i][j] = fmaf(rp[i], rv[j], oacc[i][j]);
        }
    }
    __syncthreads();

    float linv[4];
    #pragma unroll
    for (int i = 0; i < 4; i++) linv[i] = 1.0f / l_s[r0 + i];
    #pragma unroll
    for (int i = 0; i < 4; i++) {
        size_t off = (size_t)(b * SS + q0 + r0 + i) * CDIM + h * DD + c0;
        #pragma unroll
        for (int j = 0; j < 4; j++)
            ctx[off + j] = oacc[i][j] * linv[i];
    }
}

// ===========================================================================
// Launch
// ===========================================================================
extern "C" void kernel_launch(void* const* d_in, const int* in_sizes, int n_in,
                              void* d_out, int out_size)
{
    const float* hs    = (const float*)d_in[0];
    const float* ln1_w = (const float*)d_in[1];
    const float* ln1_b = (const float*)d_in[2];
    const float* q_w   = (const float*)d_in[3];
    const float* q_b   = (const float*)d_in[4];
    const float* k_w   = (const float*)d_in[5];
    const float* k_b   = (const float*)d_in[6];
    const float* v_w   = (const float*)d_in[7];
    const float* v_b   = (const float*)d_in[8];
    const float* o_w   = (const float*)d_in[9];
    const float* o_b   = (const float*)d_in[10];
    const float* lam1  = (const float*)d_in[11];
    const float* ln2_w = (const float*)d_in[12];
    const float* ln2_b = (const float*)d_in[13];
    const float* fc1_w = (const float*)d_in[14];
    const float* fc1_b = (const float*)d_in[15];
    const float* fc2_w = (const float*)d_in[16];
    const float* fc2_b = (const float*)d_in[17];
    const float* lam2  = (const float*)d_in[18];
    float* out = (float*)d_out;

    float *wqkvT, *woT, *wf1T, *wf2T, *qkvb, *xn, *qkv, *ctx, *hid, *y2, *h1;
    cudaGetSymbolAddress((void**)&wqkvT, g_wqkvT);
    cudaGetSymbolAddress((void**)&woT,   g_woT);
    cudaGetSymbolAddress((void**)&wf1T,  g_wf1T);
    cudaGetSymbolAddress((void**)&wf2T,  g_wf2T);
    cudaGetSymbolAddress((void**)&qkvb,  g_qkvb);
    cudaGetSymbolAddress((void**)&xn,    g_xn);
    cudaGetSymbolAddress((void**)&qkv,   g_qkv);
    cudaGetSymbolAddress((void**)&ctx,   g_ctx);
    cudaGetSymbolAddress((void**)&hid,   g_hid);
    cudaGetSymbolAddress((void**)&y2,    g_y2);
    cudaGetSymbolAddress((void**)&h1,    g_h1);

    // ---- weight prep ----
    dim3 tb(32, 8);
    wtrans<<<dim3(CDIM / 32, CDIM / 32), tb>>>(q_w, CDIM, CDIM, wqkvT);
    wtrans<<<dim3(CDIM / 32, CDIM / 32), tb>>>(k_w, CDIM, CDIM, wqkvT + CDIM * CDIM);
    wtrans<<<dim3(CDIM / 32, CDIM / 32), tb>>>(v_w, CDIM, CDIM, wqkvT + 2 * CDIM * CDIM);
    wtrans<<<dim3(CDIM / 32, CDIM / 32), tb>>>(o_w, CDIM, CDIM, woT);
    wtrans<<<dim3(FDIM / 32, CDIM / 32), tb>>>(fc1_w, CDIM, FDIM, wf1T);
    wtrans<<<dim3(CDIM / 32, FDIM / 32), tb>>>(fc2_w, FDIM, CDIM, wf2T);
    catbias<<<9, 256>>>(q_b, k_b, v_b, qkvb);

    cudaFuncSetAttribute(mmagemm<0>, cudaFuncAttributeMaxDynamicSharedMemorySize, GEMM_SMEM);
    cudaFuncSetAttribute(mmagemm<1>, cudaFuncAttributeMaxDynamicSharedMemorySize, GEMM_SMEM);
    cudaFuncSetAttribute(mmagemm<2>, cudaFuncAttributeMaxDynamicSharedMemorySize, GEMM_SMEM);

    // 1) LN1
    ln_kernel<<<TOK, 256>>>(hs, ln1_w, ln1_b, xn);

    // 2) fused QKV: [8192,768] x [2304,768]^T -> [8192,2304]
    mmagemm<0><<<dim3(QKVC / 128, TOK / 128), 256, GEMM_SMEM>>>(
        xn, wqkvT, qkvb, qkv, TOK, QKVC, CDIM, nullptr, nullptr);

    // 3) attention
    size_t shm = (4 * 64 * 65 + 3 * 64) * sizeof(float);
    cudaFuncSetAttribute(attn_kernel, cudaFuncAttributeMaxDynamicSharedMemorySize, (int)shm);
    attn_kernel<<<dim3(SS / 64, HH, BB), 256, shm>>>(qkv, ctx);

    // 4) O projection + lam1*. + shortcut
    mmagemm<1><<<dim3(CDIM / 128, TOK / 128), 256, GEMM_SMEM>>>(
        ctx, woT, o_b, hid, TOK, CDIM, CDIM, lam1, hs);

    // 5) LN2
    ln_kernel<<<TOK, 256>>>(hid, ln2_w, ln2_b, y2);

    // 6) FC1 + exact GELU
    mmagemm<2><<<dim3(FDIM / 128, TOK / 128), 256, GEMM_SMEM>>>(
        y2, wf1T, fc1_b, h1, TOK, FDIM, CDIM, nullptr, nullptr);

    // 7) FC2 + lam2*. + hid
    mmagemm<1><<<dim3(CDIM / 128, TOK / 128), 256, GEMM_SMEM>>>(
        h1, wf2T, fc2_b, out, TOK, CDIM, FDIM, lam2, hid);
}

// round 4
// speedup vs baseline: 1.9980x; 1.5679x over previous
#include <cuda_runtime.h>
#include <cuda_bf16.h>
#include <math.h>
#include <cstdint>

// Problem constants
#define TOK   8192      // B*S
#define CDIM  768
#define FDIM  3072
#define QKVC  2304      // 3*C
#define BB    8
#define SS    1024
#define HH    12
#define DD    64

// ===========================================================================
// Scratch (device globals -- no allocation allowed)
// ===========================================================================
__device__ __nv_bfloat16 g_wqkv_hi[QKVC * CDIM];   // [N,K]
__device__ __nv_bfloat16 g_wqkv_lo[QKVC * CDIM];
__device__ __nv_bfloat16 g_wo_hi  [CDIM * CDIM];
__device__ __nv_bfloat16 g_wo_lo  [CDIM * CDIM];
__device__ __nv_bfloat16 g_wf1_hi [FDIM * CDIM];
__device__ __nv_bfloat16 g_wf1_lo [FDIM * CDIM];
__device__ __nv_bfloat16 g_wf2_hi [CDIM * FDIM];
__device__ __nv_bfloat16 g_wf2_lo [CDIM * FDIM];
__device__ float         g_qkvb  [QKVC];
__device__ __nv_bfloat16 g_xn_hi [TOK * CDIM];
__device__ __nv_bfloat16 g_xn_lo [TOK * CDIM];
__device__ float         g_qkv   [TOK * QKVC];
__device__ __nv_bfloat16 g_ctx_hi[TOK * CDIM];
__device__ __nv_bfloat16 g_ctx_lo[TOK * CDIM];
__device__ float         g_hid   [TOK * CDIM];
__device__ __nv_bfloat16 g_y2_hi [TOK * CDIM];
__device__ __nv_bfloat16 g_y2_lo [TOK * CDIM];
__device__ __nv_bfloat16 g_h1_hi [TOK * FDIM];
__device__ __nv_bfloat16 g_h1_lo [TOK * FDIM];

// ===========================================================================
// PTX helpers (base ISA only)
// ===========================================================================
__device__ __forceinline__ uint32_t smem_u32(const void* p) {
    uint32_t a;
    asm("{ .reg .u64 t; cvta.to.shared.u64 t, %1; cvt.u32.u64 %0, t; }"
        : "=r"(a) : "l"(p));
    return a;
}
__device__ __forceinline__ void cp_async16(uint32_t s, const void* g) {
    asm volatile("cp.async.cg.shared.global [%0], [%1], 16;" :: "r"(s), "l"(g));
}
#define CP_COMMIT() asm volatile("cp.async.commit_group;")
#define CP_WAIT1()  asm volatile("cp.async.wait_group 1;")
#define CP_WAIT0()  asm volatile("cp.async.wait_group 0;")

__device__ __forceinline__ void ldm_x4(uint32_t* r, uint32_t addr) {
    asm volatile("ldmatrix.sync.aligned.m8n8.x4.shared.b16 {%0,%1,%2,%3}, [%4];"
        : "=r"(r[0]), "=r"(r[1]), "=r"(r[2]), "=r"(r[3]) : "r"(addr));
}

// D += A @ B  (m16n8k16, bf16 inputs, f32 accum)
__device__ __forceinline__ void mma_bf16(float* c, const uint32_t* a, const uint32_t* b) {
    asm volatile(
        "mma.sync.aligned.m16n8k16.row.col.f32.bf16.bf16.f32 "
        "{%0,%1,%2,%3}, {%4,%5,%6,%7}, {%8,%9}, {%0,%1,%2,%3};"
        : "+f"(c[0]), "+f"(c[1]), "+f"(c[2]), "+f"(c[3])
        : "r"(a[0]), "r"(a[1]), "r"(a[2]), "r"(a[3]), "r"(b[0]), "r"(b[1]));
}

__device__ __forceinline__ void split1(float x, __nv_bfloat16& h, __nv_bfloat16& l) {
    h = __float2bfloat16_rn(x);
    l = __float2bfloat16_rn(x - __bfloat162float(h));
}

// ===========================================================================
// Weight transpose + split: W[K,N] fp32 -> hi/lo[N,K] bf16
// ===========================================================================
__global__ __launch_bounds__(256) void wsplit(
    const float* __restrict__ W, int K, int N,
    __nv_bfloat16* __restrict__ hi, __nv_bfloat16* __restrict__ lo)
{
    __shared__ float t[32][33];
    const int n0 = blockIdx.x * 32, k0 = blockIdx.y * 32;
    const int tx = threadIdx.x, ty = threadIdx.y;   // (32, 8)
    #pragma unroll
    for (int i = 0; i < 32; i += 8)
        t[ty + i][tx] = W[(size_t)(k0 + ty + i) * N + n0 + tx];
    __syncthreads();
    #pragma unroll
    for (int i = 0; i < 32; i += 8) {
        float v = t[tx][ty + i];
        __nv_bfloat16 h, l; split1(v, h, l);
        size_t o = (size_t)(n0 + ty + i) * K + k0 + tx;
        hi[o] = h; lo[o] = l;
    }
}

__global__ void catbias(const float* __restrict__ qb, const float* __restrict__ kb,
                        const float* __restrict__ vb, float* __restrict__ out)
{
    int i = blockIdx.x * blockDim.x + threadIdx.x;
    if (i < CDIM)            out[i] = qb[i];
    else if (i < 2 * CDIM)   out[i] = kb[i - CDIM];
    else if (i < 3 * CDIM)   out[i] = vb[i - 2 * CDIM];
}

// ===========================================================================
// LayerNorm -> bf16 hi/lo. One block per token row, 256 threads.
// ===========================================================================
__global__ __launch_bounds__(256) void ln_split(
    const float* __restrict__ x, const float* __restrict__ w,
    const float* __restrict__ b,
    __nv_bfloat16* __restrict__ hi, __nv_bfloat16* __restrict__ lo)
{
    int row = blockIdx.x;
    const float* xr = x + (size_t)row * CDIM;
    float s = 0.f, s2 = 0.f;
    for (int c = threadIdx.x; c < CDIM; c += 256) {
        float v = xr[c];
        s += v; s2 += v * v;
    }
    __shared__ float sh[16];
    #pragma unroll
    for (int o = 16; o > 0; o >>= 1) {
        s  += __shfl_down_sync(0xffffffffu, s,  o);
        s2 += __shfl_down_sync(0xffffffffu, s2, o);
    }
    int warp = threadIdx.x >> 5, lane = threadIdx.x & 31;
    if (lane == 0) { sh[warp] = s; sh[warp + 8] = s2; }
    __syncthreads();
    if (threadIdx.x == 0) {
        float a = 0.f, c2 = 0.f;
        #pragma unroll
        for (int i = 0; i < 8; i++) { a += sh[i]; c2 += sh[i + 8]; }
        sh[0] = a  * (1.0f / CDIM);
        sh[8] = c2 * (1.0f / CDIM);
    }
    __syncthreads();
    float mu  = sh[0];
    float var = sh[8] - mu * mu;
    float inv = rsqrtf(var + 1e-6f);
    size_t ro = (size_t)row * CDIM;
    for (int c = threadIdx.x; c < CDIM; c += 256) {
        float v = (xr[c] - mu) * inv * w[c] + b[c];
        __nv_bfloat16 h, l; split1(v, h, l);
        hi[ro + c] = h; lo[ro + c] = l;
    }
}

// ===========================================================================
// bf16-split tensor GEMM via ldmatrix + mma.sync.
// C[M,N] = A @ B^T ; A,B given as hi/lo bf16 [rows,K].
// 128x128 CTA tile, BK=64, cp.async double buffer, 256 threads (8 warps).
// Warp w: m-half (w&1)*64, n-quarter (w>>1)*32. 3 MMAs (hh, lh, hl) per pos.
// EPI 0: +bias -> fp32 ; EPI 1: (+bias)*lam+res -> fp32 ;
// EPI 2: gelu_exact(+bias) -> bf16 hi/lo
// ===========================================================================
#define RSB   144                       // bytes per smem row (128 + 16 pad)
#define TILEB (128 * RSB)               // 18432 bytes per tile
#define GEMM_SMEM (8 * TILEB)           // 2 buffers x 4 tiles = 147456

template<int EPI>
__global__ __launch_bounds__(256) void mmagemm(
    const __nv_bfloat16* __restrict__ Ahi, const __nv_bfloat16* __restrict__ Alo,
    const __nv_bfloat16* __restrict__ Bhi, const __nv_bfloat16* __restrict__ Blo,
    const float* __restrict__ bias,
    int M, int N, int K,
    float* __restrict__ Cf,
    __nv_bfloat16* __restrict__ Chi, __nv_bfloat16* __restrict__ Clo,
    const float* __restrict__ lam, const float* __restrict__ res)
{
    extern __shared__ char smc[];
    const uint32_t sb = smem_u32(smc);

    const int tid  = threadIdx.x;
    const int wid  = tid >> 5;
    const int lane = tid & 31;
    const int wm   = wid & 1;
    const int wn   = wid >> 1;
    const int m0   = blockIdx.y * 128;
    const int n0   = blockIdx.x * 128;

    // tile base offsets within a buffer: Ahi, Alo, Bhi, Blo
    auto load_tile = [&](const __nv_bfloat16* __restrict__ G, int row0, int k0,
                         uint32_t dst) {
        #pragma unroll
        for (int i = 0; i < 4; i++) {
            int idx = tid + (i << 8);
            int r   = idx >> 3;
            int cc  = idx & 7;
            cp_async16(dst + r * RSB + cc * 16,
                       G + (size_t)(row0 + r) * K + k0 + cc * 8);
        }
    };
    auto load_chunk = [&](int k0, int p) {
        uint32_t base = sb + (uint32_t)p * (4 * TILEB);
        load_tile(Ahi, m0, k0, base);
        load_tile(Alo, m0, k0, base + TILEB);
        load_tile(Bhi, n0, k0, base + 2 * TILEB);
        load_tile(Blo, n0, k0, base + 3 * TILEB);
        CP_COMMIT();
    };

    float acc[4][4][4];
    #pragma unroll
    for (int t = 0; t < 4; t++)
        #pragma unroll
        for (int u = 0; u < 4; u++)
            #pragma unroll
            for (int e = 0; e < 4; e++) acc[t][u][e] = 0.f;

    const int nch = K >> 6;   // BK = 64
    load_chunk(0, 0);
    load_chunk(64, 1);

    // per-lane ldmatrix address components
    const int aRow = (lane & 7) + ((lane >> 3) & 1) * 8;   // + t*16 + wm*64
    const int aCol = (lane >> 4) * 16;                     // + ks*32
    const int bRow = (lane & 7) + (lane >> 4) * 8;         // + u2*16 + wn*32
    const int bCol = ((lane >> 3) & 1) * 16;               // + ks*32

    for (int it = 0; it < nch; ++it) {
        const int p = it & 1;
        if (it + 1 < nch) { CP_WAIT1(); } else { CP_WAIT0(); }
        __syncthreads();

        const uint32_t base = sb + (uint32_t)p * (4 * TILEB);
        const uint32_t sAh = base;
        const uint32_t sAl = base + TILEB;
        const uint32_t sBh = base + 2 * TILEB;
        const uint32_t sBl = base + 3 * TILEB;

        #pragma unroll
        for (int ks = 0; ks < 4; ks++) {
            const int kb = ks * 32;
            uint32_t ah[4][4], al[4][4];
            #pragma unroll
            for (int t = 0; t < 4; t++) {
                uint32_t ro = (uint32_t)((wm * 64 + t * 16 + aRow) * RSB + kb + aCol);
                ldm_x4(ah[t], sAh + ro);
                ldm_x4(al[t], sAl + ro);
            }
            uint32_t bh[2][4];
            #pragma unroll
            for (int u2 = 0; u2 < 2; u2++) {
                uint32_t ro = (uint32_t)((wn * 32 + u2 * 16 + bRow) * RSB + kb + bCol);
                ldm_x4(bh[u2], sBh + ro);
            }
            #pragma unroll
            for (int t = 0; t < 4; t++)
                #pragma unroll
                for (int u = 0; u < 4; u++) {
                    mma_bf16(acc[t][u], ah[t], &bh[u >> 1][(u & 1) * 2]);
                    mma_bf16(acc[t][u], al[t], &bh[u >> 1][(u & 1) * 2]);
                }
            uint32_t bl[2][4];
            #pragma unroll
            for (int u2 = 0; u2 < 2; u2++) {
                uint32_t ro = (uint32_t)((wn * 32 + u2 * 16 + bRow) * RSB + kb + bCol);
                ldm_x4(bl[u2], sBl + ro);
            }
            #pragma unroll
            for (int t = 0; t < 4; t++)
                #pragma unroll
                for (int u = 0; u < 4; u++)
                    mma_bf16(acc[t][u], ah[t], &bl[u >> 1][(u & 1) * 2]);
        }
        __syncthreads();
        if (it + 2 < nch) load_chunk((it + 2) << 6, p);
    }

    // Epilogue: acc[t][u] = {(r,c),(r,c+1),(r+8,c),(r+8,c+1)}
    #pragma unroll
    for (int t = 0; t < 4; t++) {
        const int rbase = m0 + wm * 64 + t * 16 + (lane >> 2);
        #pragma unroll
        for (int u = 0; u < 4; u++) {
            const int c = n0 + wn * 32 + u * 8 + (lane & 3) * 2;
            #pragma unroll
            for (int half = 0; half < 2; half++) {
                const int r = rbase + half * 8;
                const size_t ro = (size_t)r * N;
                float v0 = acc[t][u][half * 2 + 0] + bias[c];
                float v1 = acc[t][u][half * 2 + 1] + bias[c + 1];
                if (EPI == 1) {
                    v0 = v0 * lam[c]     + res[ro + c];
                    v1 = v1 * lam[c + 1] + res[ro + c + 1];
                    *(float2*)(Cf + ro + c) = make_float2(v0, v1);
                } else if (EPI == 2) {
                    v0 = 0.5f * v0 * (1.0f + erff(v0 * 0.70710678118654752f));
                    v1 = 0.5f * v1 * (1.0f + erff(v1 * 0.70710678118654752f));
                    __nv_bfloat16 h0, l0, h1, l1;
                    split1(v0, h0, l0); split1(v1, h1, l1);
                    __nv_bfloat162 hp; hp.x = h0; hp.y = h1;
                    __nv_bfloat162 lp; lp.x = l0; lp.y = l1;
                    *(__nv_bfloat162*)(Chi + ro + c) = hp;
                    *(__nv_bfloat162*)(Clo + ro + c) = lp;
                } else {
                    *(float2*)(Cf + ro + c) = make_float2(v0, v1);
                }
            }
        }
    }
}

// ===========================================================================
// Flash attention (fp32, online softmax). qkv [tok,2304] -> ctx hi/lo bf16.
// Grid: (S/64, H, B). 256 threads.
// ===========================================================================
__global__ __launch_bounds__(256) void attn_kernel(
    const float* __restrict__ qkv,
    __nv_bfloat16* __restrict__ chi, __nv_bfloat16* __restrict__ clo)
{
    extern __shared__ float smf[];
    float* qs   = smf;
    float* ks   = qs + 64 * 65;
    float* vs   = ks + 64 * 65;
    float* ss   = vs + 64 * 65;
    float* m_s  = ss + 64 * 65;
    float* l_s  = m_s + 64;
    float* al_s = l_s + 64;

    const int tid = threadIdx.x;
    const int h   = blockIdx.y;
    const int b   = blockIdx.z;
    const int q0  = blockIdx.x * 64;
    const size_t base = (size_t)b * SS * QKVC + h * DD;

    for (int i = tid; i < 64 * 16; i += 256) {
        int r = i >> 4, c4 = (i & 15) * 4;
        float4 t = *(const float4*)(qkv + base + (size_t)(q0 + r) * QKVC + c4);
        qs[r * 65 + c4 + 0] = t.x; qs[r * 65 + c4 + 1] = t.y;
        qs[r * 65 + c4 + 2] = t.z; qs[r * 65 + c4 + 3] = t.w;
    }
    if (tid < 64) { m_s[tid] = -1e30f; l_s[tid] = 0.f; }

    const int ty = tid >> 4, tx = tid & 15;
    const int r0 = ty * 4, c0 = tx * 4;
    float oacc[4][4];
    #pragma unroll
    for (int i = 0; i < 4; i++)
        #pragma unroll
        for (int j = 0; j < 4; j++) oacc[i][j] = 0.f;

    for (int j0 = 0; j0 < SS; j0 += 64) {
        __syncthreads();
        for (int i = tid; i < 64 * 16; i += 256) {
            int r = i >> 4, c4 = (i & 15) * 4;
            float4 tk = *(const float4*)(qkv + base + CDIM + (size_t)(j0 + r) * QKVC + c4);
            ks[r * 65 + c4 + 0] = tk.x; ks[r * 65 + c4 + 1] = tk.y;
            ks[r * 65 + c4 + 2] = tk.z; ks[r * 65 + c4 + 3] = tk.w;
            float4 tv = *(const float4*)(qkv + base + 2 * CDIM + (size_t)(j0 + r) * QKVC + c4);
            vs[r * 65 + c4 + 0] = tv.x; vs[r * 65 + c4 + 1] = tv.y;
            vs[r * 65 + c4 + 2] = tv.z; vs[r * 65 + c4 + 3] = tv.w;
        }
        __syncthreads();

        float sa[4][4];
        #pragma unroll
        for (int i = 0; i < 4; i++)
            #pragma unroll
            for (int j = 0; j < 4; j++) sa[i][j] = 0.f;

        #pragma unroll 8
        for (int kk = 0; kk < 64; kk++) {
            float ra[4], rb[4];
            #pragma unroll
            for (int i = 0; i < 4; i++) ra[i] = qs[(r0 + i) * 65 + kk];
            #pragma unroll
            for (int j = 0; j < 4; j++) rb[j] = ks[(c0 + j) * 65 + kk];
            #pragma unroll
            for (int i = 0; i < 4; i++)
                #pragma unroll
                for (int j = 0; j < 4; j++)
                    sa[i][j] = fmaf(ra[i], rb[j], sa[i][j]);
        }
        #pragma unroll
        for (int i = 0; i < 4; i++)
            #pragma unroll
            for (int j = 0; j < 4; j++)
                ss[(r0 + i) * 65 + c0 + j] = sa[i][j] * 0.125f;
        __syncthreads();

        if (tid < 64) {
            int r = tid;
            float mold = m_s[r];
            float tmax = -1e30f;
            #pragma unroll 8
            for (int c = 0; c < 64; c++) tmax = fmaxf(tmax, ss[r * 65 + c]);
            float mnew = fmaxf(mold, tmax);
            float a = __expf(mold - mnew);
            float sum = 0.f;
            #pragma unroll 8
            for (int c = 0; c < 64; c++) {
                float pcur = __expf(ss[r * 65 + c] - mnew);
                ss[r * 65 + c] = pcur;
                sum += pcur;
            }
            l_s[r]  = l_s[r] * a + sum;
            m_s[r]  = mnew;
            al_s[r] = a;
        }
        __syncthreads();

        float ar[4];
        #pragma unroll
        for (int i = 0; i < 4; i++) ar[i] = al_s[r0 + i];
        #pragma unroll
        for (int i = 0; i < 4; i++)
            #pragma unroll
            for (int j = 0; j < 4; j++) oacc[i][j] *= ar[i];

        #pragma unroll 8
        for (int kk = 0; kk < 64; kk++) {
            float rp[4], rv[4];
            #pragma unroll
            for (int i = 0; i < 4; i++) rp[i] = ss[(r0 + i) * 65 + kk];
            #pragma unroll
            for (int j = 0; j < 4; j++) rv[j] = vs[kk * 65 + c0 + j];
            #pragma unroll
            for (int i = 0; i < 4; i++)
                #pragma unroll
                for (int j = 0; j < 4; j++)
                    oacc[i][j] = fmaf(rp[i], rv[j], oacc[i][j]);
        }
    }
    __syncthreads();

    float linv[4];
    #pragma unroll
    for (int i = 0; i < 4; i++) linv[i] = 1.0f / l_s[r0 + i];
    #pragma unroll
    for (int i = 0; i < 4; i++) {
        size_t off = (size_t)(b * SS + q0 + r0 + i) * CDIM + h * DD + c0;
        #pragma unroll
        for (int j = 0; j < 4; j++) {
            float v = oacc[i][j] * linv[i];
            __nv_bfloat16 hb, lb; split1(v, hb, lb);
            chi[off + j] = hb;
            clo[off + j] = lb;
        }
    }
}

// ===========================================================================
// Launch
// ===========================================================================
extern "C" void kernel_launch(void* const* d_in, const int* in_sizes, int n_in,
                              void* d_out, int out_size)
{
    const float* hs    = (const float*)d_in[0];
    const float* ln1_w = (const float*)d_in[1];
    const float* ln1_b = (const float*)d_in[2];
    const float* q_w   = (const float*)d_in[3];
    const float* q_b   = (const float*)d_in[4];
    const float* k_w   = (const float*)d_in[5];
    const float* k_b   = (const float*)d_in[6];
    const float* v_w   = (const float*)d_in[7];
    const float* v_b   = (const float*)d_in[8];
    const float* o_w   = (const float*)d_in[9];
    const float* o_b   = (const float*)d_in[10];
    const float* lam1  = (const float*)d_in[11];
    const float* ln2_w = (const float*)d_in[12];
    const float* ln2_b = (const float*)d_in[13];
    const float* fc1_w = (const float*)d_in[14];
    const float* fc1_b = (const float*)d_in[15];
    const float* fc2_w = (const float*)d_in[16];
    const float* fc2_b = (const float*)d_in[17];
    const float* lam2  = (const float*)d_in[18];
    float* out = (float*)d_out;

    __nv_bfloat16 *wqkv_hi, *wqkv_lo, *wo_hi, *wo_lo, *wf1_hi, *wf1_lo, *wf2_hi, *wf2_lo;
    __nv_bfloat16 *xn_hi, *xn_lo, *ctx_hi, *ctx_lo, *y2_hi, *y2_lo, *h1_hi, *h1_lo;
    float *qkvb, *qkv, *hid;
    cudaGetSymbolAddress((void**)&wqkv_hi, g_wqkv_hi);
    cudaGetSymbolAddress((void**)&wqkv_lo, g_wqkv_lo);
    cudaGetSymbolAddress((void**)&wo_hi,   g_wo_hi);
    cudaGetSymbolAddress((void**)&wo_lo,   g_wo_lo);
    cudaGetSymbolAddress((void**)&wf1_hi,  g_wf1_hi);
    cudaGetSymbolAddress((void**)&wf1_lo,  g_wf1_lo);
    cudaGetSymbolAddress((void**)&wf2_hi,  g_wf2_hi);
    cudaGetSymbolAddress((void**)&wf2_lo,  g_wf2_lo);
    cudaGetSymbolAddress((void**)&qkvb,    g_qkvb);
    cudaGetSymbolAddress((void**)&xn_hi,   g_xn_hi);
    cudaGetSymbolAddress((void**)&xn_lo,   g_xn_lo);
    cudaGetSymbolAddress((void**)&qkv,     g_qkv);
    cudaGetSymbolAddress((void**)&ctx_hi,  g_ctx_hi);
    cudaGetSymbolAddress((void**)&ctx_lo,  g_ctx_lo);
    cudaGetSymbolAddress((void**)&hid,     g_hid);
    cudaGetSymbolAddress((void**)&y2_hi,   g_y2_hi);
    cudaGetSymbolAddress((void**)&y2_lo,   g_y2_lo);
    cudaGetSymbolAddress((void**)&h1_hi,   g_h1_hi);
    cudaGetSymbolAddress((void**)&h1_lo,   g_h1_lo);

    // ---- weight prep ----
    dim3 tb(32, 8);
    wsplit<<<dim3(CDIM / 32, CDIM / 32), tb>>>(q_w, CDIM, CDIM, wqkv_hi, wqkv_lo);
    wsplit<<<dim3(CDIM / 32, CDIM / 32), tb>>>(k_w, CDIM, CDIM, wqkv_hi + CDIM * CDIM, wqkv_lo + CDIM * CDIM);
    wsplit<<<dim3(CDIM / 32, CDIM / 32), tb>>>(v_w, CDIM, CDIM, wqkv_hi + 2 * CDIM * CDIM, wqkv_lo + 2 * CDIM * CDIM);
    wsplit<<<dim3(CDIM / 32, CDIM / 32), tb>>>(o_w, CDIM, CDIM, wo_hi, wo_lo);
    wsplit<<<dim3(FDIM / 32, CDIM / 32), tb>>>(fc1_w, CDIM, FDIM, wf1_hi, wf1_lo);
    wsplit<<<dim3(CDIM / 32, FDIM / 32), tb>>>(fc2_w, FDIM, CDIM, wf2_hi, wf2_lo);
    catbias<<<9, 256>>>(q_b, k_b, v_b, qkvb);

    cudaFuncSetAttribute(mmagemm<0>, cudaFuncAttributeMaxDynamicSharedMemorySize, GEMM_SMEM);
    cudaFuncSetAttribute(mmagemm<1>, cudaFuncAttributeMaxDynamicSharedMemorySize, GEMM_SMEM);
    cudaFuncSetAttribute(mmagemm<2>, cudaFuncAttributeMaxDynamicSharedMemorySize, GEMM_SMEM);

    // 1) LN1 -> bf16 split
    ln_split<<<TOK, 256>>>(hs, ln1_w, ln1_b, xn_hi, xn_lo);

    // 2) fused QKV: [8192,768] x [2304,768]^T -> fp32 [8192,2304]
    mmagemm<0><<<dim3(QKVC / 128, TOK / 128), 256, GEMM_SMEM>>>(
        xn_hi, xn_lo, wqkv_hi, wqkv_lo, qkvb, TOK, QKVC, CDIM,
        qkv, nullptr, nullptr, nullptr, nullptr);

    // 3) attention -> ctx hi/lo
    size_t shm = (4 * 64 * 65 + 3 * 64) * sizeof(float);
    cudaFuncSetAttribute(attn_kernel, cudaFuncAttributeMaxDynamicSharedMemorySize, (int)shm);
    attn_kernel<<<dim3(SS / 64, HH, BB), 256, shm>>>(qkv, ctx_hi, ctx_lo);

    // 4) O projection + lam1*. + shortcut -> hid fp32
    mmagemm<1><<<dim3(CDIM / 128, TOK / 128), 256, GEMM_SMEM>>>(
        ctx_hi, ctx_lo, wo_hi, wo_lo, o_b, TOK, CDIM, CDIM,
        hid, nullptr, nullptr, lam1, hs);

    // 5) LN2 -> bf16 split
    ln_split<<<TOK, 256>>>(hid, ln2_w, ln2_b, y2_hi, y2_lo);

    // 6) FC1 + exact GELU -> h1 hi/lo
    mmagemm<2><<<dim3(FDIM / 128, TOK / 128), 256, GEMM_SMEM>>>(
        y2_hi, y2_lo, wf1_hi, wf1_lo, fc1_b, TOK, FDIM, CDIM,
        nullptr, h1_hi, h1_lo, nullptr, nullptr);

    // 7) FC2 + lam2*. + hid -> out fp32
    mmagemm<1><<<dim3(CDIM / 128, TOK / 128), 256, GEMM_SMEM>>>(
        h1_hi, h1_lo, wf2_hi, wf2_lo, fc2_b, TOK, CDIM, FDIM,
        out, nullptr, nullptr, lam2, hid);
}

// round 5
// speedup vs baseline: 2.8838x; 1.4433x over previous
#include <cuda_runtime.h>
#include <cuda_bf16.h>
#include <math.h>
#include <cstdint>

// Problem constants
#define TOK   8192      // B*S
#define CDIM  768
#define FDIM  3072
#define QKVC  2304      // 3*C
#define BB    8
#define SS    1024
#define HH    12
#define DD    64

// ===========================================================================
// Scratch (device globals -- no allocation allowed)
// ===========================================================================
__device__ __nv_bfloat16 g_wqkv_hi[QKVC * CDIM];   // [N,K]
__device__ __nv_bfloat16 g_wqkv_lo[QKVC * CDIM];
__device__ __nv_bfloat16 g_wo_hi  [CDIM * CDIM];
__device__ __nv_bfloat16 g_wo_lo  [CDIM * CDIM];
__device__ __nv_bfloat16 g_wf1_hi [FDIM * CDIM];
__device__ __nv_bfloat16 g_wf1_lo [FDIM * CDIM];
__device__ __nv_bfloat16 g_wf2_hi [CDIM * FDIM];
__device__ __nv_bfloat16 g_wf2_lo [CDIM * FDIM];
__device__ float         g_qkvb  [QKVC];
__device__ __nv_bfloat16 g_xn_hi [TOK * CDIM];
__device__ __nv_bfloat16 g_xn_lo [TOK * CDIM];
__device__ __nv_bfloat16 g_qkv_hi[TOK * QKVC];
__device__ __nv_bfloat16 g_qkv_lo[TOK * QKVC];
__device__ __nv_bfloat16 g_ctx_hi[TOK * CDIM];
__device__ __nv_bfloat16 g_ctx_lo[TOK * CDIM];
__device__ float         g_hid   [TOK * CDIM];
__device__ __nv_bfloat16 g_y2_hi [TOK * CDIM];
__device__ __nv_bfloat16 g_y2_lo [TOK * CDIM];
__device__ __nv_bfloat16 g_h1_hi [TOK * FDIM];
__device__ __nv_bfloat16 g_h1_lo [TOK * FDIM];

// ===========================================================================
// PTX helpers (base ISA only)
// ===========================================================================
__device__ __forceinline__ uint32_t smem_u32(const void* p) {
    uint32_t a;
    asm("{ .reg .u64 t; cvta.to.shared.u64 t, %1; cvt.u32.u64 %0, t; }"
        : "=r"(a) : "l"(p));
    return a;
}
__device__ __forceinline__ void cp_async16(uint32_t s, const void* g) {
    asm volatile("cp.async.cg.shared.global [%0], [%1], 16;" :: "r"(s), "l"(g));
}
#define CP_COMMIT() asm volatile("cp.async.commit_group;")
#define CP_WAIT2()  asm volatile("cp.async.wait_group 2;")
#define CP_WAIT1()  asm volatile("cp.async.wait_group 1;")
#define CP_WAIT0()  asm volatile("cp.async.wait_group 0;")

__device__ __forceinline__ void ldm_x4(uint32_t* r, uint32_t addr) {
    asm volatile("ldmatrix.sync.aligned.m8n8.x4.shared.b16 {%0,%1,%2,%3}, [%4];"
        : "=r"(r[0]), "=r"(r[1]), "=r"(r[2]), "=r"(r[3]) : "r"(addr));
}
__device__ __forceinline__ void ldm_x4t(uint32_t* r, uint32_t addr) {
    asm volatile("ldmatrix.sync.aligned.m8n8.x4.trans.shared.b16 {%0,%1,%2,%3}, [%4];"
        : "=r"(r[0]), "=r"(r[1]), "=r"(r[2]), "=r"(r[3]) : "r"(addr));
}

// D += A @ B  (m16n8k16, bf16 inputs, f32 accum)
__device__ __forceinline__ void mma_bf16(float* c, const uint32_t* a, const uint32_t* b) {
    asm volatile(
        "mma.sync.aligned.m16n8k16.row.col.f32.bf16.bf16.f32 "
        "{%0,%1,%2,%3}, {%4,%5,%6,%7}, {%8,%9}, {%0,%1,%2,%3};"
        : "+f"(c[0]), "+f"(c[1]), "+f"(c[2]), "+f"(c[3])
        : "r"(a[0]), "r"(a[1]), "r"(a[2]), "r"(a[3]), "r"(b[0]), "r"(b[1]));
}

__device__ __forceinline__ void split1(float x, __nv_bfloat16& h, __nv_bfloat16& l) {
    h = __float2bfloat16_rn(x);
    l = __float2bfloat16_rn(x - __bfloat162float(h));
}
__device__ __forceinline__ uint32_t pack_bf(float x, float y) {
    __nv_bfloat162 t = __floats2bfloat162_rn(x, y);
    return *(uint32_t*)&t;
}
__device__ __forceinline__ void split_pack(float x, float y, uint32_t& hi, uint32_t& lo) {
    __nv_bfloat16 hx, lx, hy, ly;
    split1(x, hx, lx); split1(y, hy, ly);
    __nv_bfloat162 hp; hp.x = hx; hp.y = hy;
    __nv_bfloat162 lp; lp.x = lx; lp.y = ly;
    hi = *(uint32_t*)&hp; lo = *(uint32_t*)&lp;
}

// ===========================================================================
// Weight transpose + split: W[K,N] fp32 -> hi/lo[N,K] bf16
// ===========================================================================
__global__ __launch_bounds__(256) void wsplit(
    const float* __restrict__ W, int K, int N,
    __nv_bfloat16* __restrict__ hi, __nv_bfloat16* __restrict__ lo)
{
    __shared__ float t[32][33];
    const int n0 = blockIdx.x * 32, k0 = blockIdx.y * 32;
    const int tx = threadIdx.x, ty = threadIdx.y;   // (32, 8)
    #pragma unroll
    for (int i = 0; i < 32; i += 8)
        t[ty + i][tx] = W[(size_t)(k0 + ty + i) * N + n0 + tx];
    __syncthreads();
    #pragma unroll
    for (int i = 0; i < 32; i += 8) {
        float v = t[tx][ty + i];
        __nv_bfloat16 h, l; split1(v, h, l);
        size_t o = (size_t)(n0 + ty + i) * K + k0 + tx;
        hi[o] = h; lo[o] = l;
    }
}

__global__ void catbias(const float* __restrict__ qb, const float* __restrict__ kb,
                        const float* __restrict__ vb, float* __restrict__ out)
{
    int i = blockIdx.x * blockDim.x + threadIdx.x;
    if (i < CDIM)            out[i] = qb[i];
    else if (i < 2 * CDIM)   out[i] = kb[i - CDIM];
    else if (i < 3 * CDIM)   out[i] = vb[i - 2 * CDIM];
}

// ===========================================================================
// LayerNorm -> bf16 hi/lo. One block per token row, 256 threads.
// ===========================================================================
__global__ __launch_bounds__(256) void ln_split(
    const float* __restrict__ x, const float* __restrict__ w,
    const float* __restrict__ b,
    __nv_bfloat16* __restrict__ hi, __nv_bfloat16* __restrict__ lo)
{
    int row = blockIdx.x;
    const float* xr = x + (size_t)row * CDIM;
    float s = 0.f, s2 = 0.f;
    for (int c = threadIdx.x; c < CDIM; c += 256) {
        float v = xr[c];
        s += v; s2 += v * v;
    }
    __shared__ float sh[16];
    #pragma unroll
    for (int o = 16; o > 0; o >>= 1) {
        s  += __shfl_down_sync(0xffffffffu, s,  o);
        s2 += __shfl_down_sync(0xffffffffu, s2, o);
    }
    int warp = threadIdx.x >> 5, lane = threadIdx.x & 31;
    if (lane == 0) { sh[warp] = s; sh[warp + 8] = s2; }
    __syncthreads();
    if (threadIdx.x == 0) {
        float a = 0.f, c2 = 0.f;
        #pragma unroll
        for (int i = 0; i < 8; i++) { a += sh[i]; c2 += sh[i + 8]; }
        sh[0] = a  * (1.0f / CDIM);
        sh[8] = c2 * (1.0f / CDIM);
    }
    __syncthreads();
    float mu  = sh[0];
    float var = sh[8] - mu * mu;
    float inv = rsqrtf(var + 1e-6f);
    size_t ro = (size_t)row * CDIM;
    for (int c = threadIdx.x; c < CDIM; c += 256) {
        float v = (xr[c] - mu) * inv * w[c] + b[c];
        __nv_bfloat16 h, l; split1(v, h, l);
        hi[ro + c] = h; lo[ro + c] = l;
    }
}

// ===========================================================================
// bf16-split tensor GEMM via ldmatrix + mma.sync.
// C[M,N] = A @ B^T ; A,B given as hi/lo bf16 [rows,K].
// 128x128 CTA tile, BK=64, cp.async double buffer, 256 threads (8 warps).
// EPI 0: +bias -> fp32 ; EPI 1: (+bias)*lam+res -> fp32 ;
// EPI 2: gelu_exact(+bias) -> bf16 hi/lo ; EPI 3: +bias -> bf16 hi/lo
// ===========================================================================
#define RSB   144                       // bytes per smem row (128 + 16 pad)
#define TILEB (128 * RSB)               // 18432 bytes per tile
#define GEMM_SMEM (8 * TILEB)           // 2 buffers x 4 tiles = 147456

template<int EPI>
__global__ __launch_bounds__(256) void mmagemm(
    const __nv_bfloat16* __restrict__ Ahi, const __nv_bfloat16* __restrict__ Alo,
    const __nv_bfloat16* __restrict__ Bhi, const __nv_bfloat16* __restrict__ Blo,
    const float* __restrict__ bias,
    int M, int N, int K,
    float* __restrict__ Cf,
    __nv_bfloat16* __restrict__ Chi, __nv_bfloat16* __restrict__ Clo,
    const float* __restrict__ lam, const float* __restrict__ res)
{
    extern __shared__ char smc[];
    const uint32_t sb = smem_u32(smc);

    const int tid  = threadIdx.x;
    const int wid  = tid >> 5;
    const int lane = tid & 31;
    const int wm   = wid & 1;
    const int wn   = wid >> 1;
    const int m0   = blockIdx.y * 128;
    const int n0   = blockIdx.x * 128;

    auto load_tile = [&](const __nv_bfloat16* __restrict__ G, int row0, int k0,
                         uint32_t dst) {
        #pragma unroll
        for (int i = 0; i < 4; i++) {
            int idx = tid + (i << 8);
            int r   = idx >> 3;
            int cc  = idx & 7;
            cp_async16(dst + r * RSB + cc * 16,
                       G + (size_t)(row0 + r) * K + k0 + cc * 8);
        }
    };
    auto load_chunk = [&](int k0, int p) {
        uint32_t base = sb + (uint32_t)p * (4 * TILEB);
        load_tile(Ahi, m0, k0, base);
        load_tile(Alo, m0, k0, base + TILEB);
        load_tile(Bhi, n0, k0, base + 2 * TILEB);
        load_tile(Blo, n0, k0, base + 3 * TILEB);
        CP_COMMIT();
    };

    float acc[4][4][4];
    #pragma unroll
    for (int t = 0; t < 4; t++)
        #pragma unroll
        for (int u = 0; u < 4; u++)
            #pragma unroll
            for (int e = 0; e < 4; e++) acc[t][u][e] = 0.f;

    const int nch = K >> 6;   // BK = 64
    load_chunk(0, 0);
    load_chunk(64, 1);

    const int aRow = (lane & 7) + ((lane >> 3) & 1) * 8;
    const int aCol = (lane >> 4) * 16;
    const int bRow = (lane & 7) + (lane >> 4) * 8;
    const int bCol = ((lane >> 3) & 1) * 16;

    for (int it = 0; it < nch; ++it) {
        const int p = it & 1;
        if (it + 1 < nch) { CP_WAIT1(); } else { CP_WAIT0(); }
        __syncthreads();

        const uint32_t base = sb + (uint32_t)p * (4 * TILEB);
        const uint32_t sAh = base;
        const uint32_t sAl = base + TILEB;
        const uint32_t sBh = base + 2 * TILEB;
        const uint32_t sBl = base + 3 * TILEB;

        #pragma unroll
        for (int ks = 0; ks < 4; ks++) {
            const int kb = ks * 32;
            uint32_t ah[4][4], al[4][4];
            #pragma unroll
            for (int t = 0; t < 4; t++) {
                uint32_t ro = (uint32_t)((wm * 64 + t * 16 + aRow) * RSB + kb + aCol);
                ldm_x4(ah[t], sAh + ro);
                ldm_x4(al[t], sAl + ro);
            }
            uint32_t bh[2][4];
            #pragma unroll
            for (int u2 = 0; u2 < 2; u2++) {
                uint32_t ro = (uint32_t)((wn * 32 + u2 * 16 + bRow) * RSB + kb + bCol);
                ldm_x4(bh[u2], sBh + ro);
            }
            #pragma unroll
            for (int t = 0; t < 4; t++)
                #pragma unroll
                for (int u = 0; u < 4; u++) {
                    mma_bf16(acc[t][u], ah[t], &bh[u >> 1][(u & 1) * 2]);
                    mma_bf16(acc[t][u], al[t], &bh[u >> 1][(u & 1) * 2]);
                }
            uint32_t bl[2][4];
            #pragma unroll
            for (int u2 = 0; u2 < 2; u2++) {
                uint32_t ro = (uint32_t)((wn * 32 + u2 * 16 + bRow) * RSB + kb + bCol);
                ldm_x4(bl[u2], sBl + ro);
            }
            #pragma unroll
            for (int t = 0; t < 4; t++)
                #pragma unroll
                for (int u = 0; u < 4; u++)
                    mma_bf16(acc[t][u], ah[t], &bl[u >> 1][(u & 1) * 2]);
        }
        __syncthreads();
        if (it + 2 < nch) load_chunk((it + 2) << 6, p);
    }

    #pragma unroll
    for (int t = 0; t < 4; t++) {
        const int rbase = m0 + wm * 64 + t * 16 + (lane >> 2);
        #pragma unroll
        for (int u = 0; u < 4; u++) {
            const int c = n0 + wn * 32 + u * 8 + (lane & 3) * 2;
            #pragma unroll
            for (int half = 0; half < 2; half++) {
                const int r = rbase + half * 8;
                const size_t ro = (size_t)r * N;
                float v0 = acc[t][u][half * 2 + 0] + bias[c];
                float v1 = acc[t][u][half * 2 + 1] + bias[c + 1];
                if (EPI == 1) {
                    v0 = v0 * lam[c]     + res[ro + c];
                    v1 = v1 * lam[c + 1] + res[ro + c + 1];
                    *(float2*)(Cf + ro + c) = make_float2(v0, v1);
                } else if (EPI == 2 || EPI == 3) {
                    if (EPI == 2) {
                        v0 = 0.5f * v0 * (1.0f + erff(v0 * 0.70710678118654752f));
                        v1 = 0.5f * v1 * (1.0f + erff(v1 * 0.70710678118654752f));
                    }
                    uint32_t hp, lp;
                    split_pack(v0, v1, hp, lp);
                    *(uint32_t*)(Chi + ro + c) = hp;
                    *(uint32_t*)(Clo + ro + c) = lp;
                } else {
                    *(float2*)(Cf + ro + c) = make_float2(v0, v1);
                }
            }
        }
    }
}

// ===========================================================================
// Flash attention on tensor cores (bf16-split, online softmax).
// Inputs: qkv hi/lo bf16 [tok, 2304]; output ctx hi/lo bf16 [tok, 768].
// Grid: (S/64, H, B), 128 threads (4 warps x m16 q-rows). BN = 64 keys/iter.
// ===========================================================================
#define AT_Q    0                        // Qhi, Qlo: 2 x 9216
#define AT_BUF  18432                    // 2 buffers x (Khi,Klo,Vhi,Vlo) x 9216
#define AT_TILE 9216                     // 64 rows x 144 B
#define ATT_SMEM (18432 + 2 * 4 * 9216)  // 92160

__global__ __launch_bounds__(128) void attn_mma(
    const __nv_bfloat16* __restrict__ qhi, const __nv_bfloat16* __restrict__ qlo,
    __nv_bfloat16* __restrict__ chi, __nv_bfloat16* __restrict__ clo)
{
    extern __shared__ char smc[];
    const uint32_t sb = smem_u32(smc);
    const int tid  = threadIdx.x;
    const int wid  = tid >> 5;
    const int lane = tid & 31;
    const int h    = blockIdx.y;
    const int b    = blockIdx.z;
    const int q0   = blockIdx.x * 64;

    // ---- load Q tile (64 x 64 bf16, hi+lo) ----
    for (int i = tid; i < 512; i += 128) {
        int r = i >> 3, c = i & 7;
        size_t g = (size_t)(b * SS + q0 + r) * QKVC + h * DD + c * 8;
        cp_async16(sb + AT_Q + r * RSB + c * 16, qhi + g);
        cp_async16(sb + AT_Q + AT_TILE + r * RSB + c * 16, qlo + g);
    }
    CP_COMMIT();

    auto load_kv = [&](int j0, int p) {
        uint32_t base = sb + AT_BUF + (uint32_t)p * (4 * AT_TILE);
        for (int i = tid; i < 512; i += 128) {
            int r = i >> 3, c = i & 7;
            size_t gk = (size_t)(b * SS + j0 + r) * QKVC + CDIM + h * DD + c * 8;
            size_t gv = gk + CDIM;
            cp_async16(base + r * RSB + c * 16,                qhi + gk);
            cp_async16(base + AT_TILE + r * RSB + c * 16,      qlo + gk);
            cp_async16(base + 2 * AT_TILE + r * RSB + c * 16,  qhi + gv);
            cp_async16(base + 3 * AT_TILE + r * RSB + c * 16,  qlo + gv);
        }
        CP_COMMIT();
    };
    load_kv(0, 0);
    load_kv(64, 1);

    // fragment address components
    const int aRow = (lane & 7) + ((lane >> 3) & 1) * 8;   // A (Q): + t16
    const int aCol = (lane >> 4) * 16;
    const int bRow = (lane & 7) + (lane >> 4) * 8;         // B (K): + n16 group
    const int bCol = ((lane >> 3) & 1) * 16;
    const int vRow = (lane & 7) + ((lane >> 3) & 1) * 8;   // V trans: + k16 group
    const int vCol = (lane >> 4) * 16;

    // wait Q (2 kv groups may still be pending)
    CP_WAIT2();
    __syncthreads();

    uint32_t qh[4][4], ql[4][4];
    #pragma unroll
    for (int ks = 0; ks < 4; ks++) {
        uint32_t ro = (uint32_t)((wid * 16 + aRow) * RSB + ks * 32 + aCol);
        ldm_x4(qh[ks], sb + AT_Q + ro);
        ldm_x4(ql[ks], sb + AT_Q + AT_TILE + ro);
    }

    float oacc[8][4];
    #pragma unroll
    for (int u = 0; u < 8; u++)
        #pragma unroll
        for (int e = 0; e < 4; e++) oacc[u][e] = 0.f;
    float m0 = -1e30f, m1 = -1e30f, l0 = 0.f, l1 = 0.f;

    const int nt = SS / 64;   // 16
    for (int it = 0; it < nt; ++it) {
        const int p = it & 1;
        if (it + 1 < nt) { CP_WAIT1(); } else { CP_WAIT0(); }
        __syncthreads();

        const uint32_t base = sb + AT_BUF + (uint32_t)p * (4 * AT_TILE);
        const uint32_t sKh = base;
        const uint32_t sKl = base + AT_TILE;
        const uint32_t sVh = base + 2 * AT_TILE;
        const uint32_t sVl = base + 3 * AT_TILE;

        // ---- S = Q @ K^T (bf16 split) ----
        float sacc[8][4];
        #pragma unroll
        for (int u = 0; u < 8; u++)
            #pragma unroll
            for (int e = 0; e < 4; e++) sacc[u][e] = 0.f;

        #pragma unroll
        for (int ks = 0; ks < 4; ks++) {
            const int kb = ks * 32;
            uint32_t kh[4][4], kl[4][4];
            #pragma unroll
            for (int g = 0; g < 4; g++) {
                uint32_t ro = (uint32_t)((g * 16 + bRow) * RSB + kb + bCol);
                ldm_x4(kh[g], sKh + ro);
                ldm_x4(kl[g], sKl + ro);
            }
            #pragma unroll
            for (int g = 0; g < 4; g++)
                #pragma unroll
                for (int hf = 0; hf < 2; hf++) {
                    int u = g * 2 + hf;
                    mma_bf16(sacc[u], qh[ks], &kh[g][hf * 2]);
                    mma_bf16(sacc[u], ql[ks], &kh[g][hf * 2]);
                    mma_bf16(sacc[u], qh[ks], &kl[g][hf * 2]);
                }
        }

        // ---- online softmax on fragments ----
        float mx0 = m0, mx1 = m1;
        #pragma unroll
        for (int u = 0; u < 8; u++) {
            sacc[u][0] *= 0.125f; sacc[u][1] *= 0.125f;
            sacc[u][2] *= 0.125f; sacc[u][3] *= 0.125f;
            mx0 = fmaxf(mx0, fmaxf(sacc[u][0], sacc[u][1]));
            mx1 = fmaxf(mx1, fmaxf(sacc[u][2], sacc[u][3]));
        }
        mx0 = fmaxf(mx0, __shfl_xor_sync(0xffffffffu, mx0, 1));
        mx0 = fmaxf(mx0, __shfl_xor_sync(0xffffffffu, mx0, 2));
        mx1 = fmaxf(mx1, __shfl_xor_sync(0xffffffffu, mx1, 1));
        mx1 = fmaxf(mx1, __shfl_xor_sync(0xffffffffu, mx1, 2));
        float al0 = __expf(m0 - mx0), al1 = __expf(m1 - mx1);
        m0 = mx0; m1 = mx1;
        float sum0 = 0.f, sum1 = 0.f;
        #pragma unroll
        for (int u = 0; u < 8; u++) {
            sacc[u][0] = __expf(sacc[u][0] - m0);
            sacc[u][1] = __expf(sacc[u][1] - m0);
            sacc[u][2] = __expf(sacc[u][2] - m1);
            sacc[u][3] = __expf(sacc[u][3] - m1);
            sum0 += sacc[u][0] + sacc[u][1];
            sum1 += sacc[u][2] + sacc[u][3];
        }
        sum0 += __shfl_xor_sync(0xffffffffu, sum0, 1);
        sum0 += __shfl_xor_sync(0xffffffffu, sum0, 2);
        sum1 += __shfl_xor_sync(0xffffffffu, sum1, 1);
        sum1 += __shfl_xor_sync(0xffffffffu, sum1, 2);
        l0 = l0 * al0 + sum0;
        l1 = l1 * al1 + sum1;
        #pragma unroll
        for (int u = 0; u < 8; u++) {
            oacc[u][0] *= al0; oacc[u][1] *= al0;
            oacc[u][2] *= al1; oacc[u][3] *= al1;
        }

        // ---- P fragments (split) ----
        uint32_t ph[4][4], pl[4][4];
        #pragma unroll
        for (int t = 0; t < 4; t++) {
            split_pack(sacc[2*t][0],   sacc[2*t][1],   ph[t][0], pl[t][0]);
            split_pack(sacc[2*t][2],   sacc[2*t][3],   ph[t][1], pl[t][1]);
            split_pack(sacc[2*t+1][0], sacc[2*t+1][1], ph[t][2], pl[t][2]);
            split_pack(sacc[2*t+1][2], sacc[2*t+1][3], ph[t][3], pl[t][3]);
        }

        // ---- O += P @ V (bf16 split; V via ldmatrix.trans) ----
        #pragma unroll
        for (int t = 0; t < 4; t++) {
            uint32_t vh[4][4], vl[4][4];
            #pragma unroll
            for (int g = 0; g < 4; g++) {
                uint32_t ro = (uint32_t)((t * 16 + vRow) * RSB + g * 32 + vCol);
                ldm_x4t(vh[g], sVh + ro);
                ldm_x4t(vl[g], sVl + ro);
            }
            #pragma unroll
            for (int g = 0; g < 4; g++)
                #pragma unroll
                for (int hf = 0; hf < 2; hf++) {
                    int u = g * 2 + hf;
                    mma_bf16(oacc[u], ph[t], &vh[g][hf * 2]);
                    mma_bf16(oacc[u], pl[t], &vh[g][hf * 2]);
                    mma_bf16(oacc[u], ph[t], &vl[g][hf * 2]);
                }
        }

        __syncthreads();
        if (it + 2 < nt) load_kv((it + 2) * 64, p);
    }

    // ---- normalize + write ctx hi/lo ----
    float inv0 = 1.0f / l0, inv1 = 1.0f / l1;
    const int r  = lane >> 2;
    const int cc = (lane & 3) * 2;
    #pragma unroll
    for (int u = 0; u < 8; u++) {
        int col = h * DD + u * 8 + cc;
        size_t o0 = (size_t)(b * SS + q0 + wid * 16 + r)     * CDIM + col;
        size_t o1 = (size_t)(b * SS + q0 + wid * 16 + r + 8) * CDIM + col;
        uint32_t hp, lp;
        split_pack(oacc[u][0] * inv0, oacc[u][1] * inv0, hp, lp);
        *(uint32_t*)(chi + o0) = hp;
        *(uint32_t*)(clo + o0) = lp;
        split_pack(oacc[u][2] * inv1, oacc[u][3] * inv1, hp, lp);
        *(uint32_t*)(chi + o1) = hp;
        *(uint32_t*)(clo + o1) = lp;
    }
}

// ===========================================================================
// Launch
// ===========================================================================
extern "C" void kernel_launch(void* const* d_in, const int* in_sizes, int n_in,
                              void* d_out, int out_size)
{
    const float* hs    = (const float*)d_in[0];
    const float* ln1_w = (const float*)d_in[1];
    const float* ln1_b = (const float*)d_in[2];
    const float* q_w   = (const float*)d_in[3];
    const float* q_b   = (const float*)d_in[4];
    const float* k_w   = (const float*)d_in[5];
    const float* k_b   = (const float*)d_in[6];
    const float* v_w   = (const float*)d_in[7];
    const float* v_b   = (const float*)d_in[8];
    const float* o_w   = (const float*)d_in[9];
    const float* o_b   = (const float*)d_in[10];
    const float* lam1  = (const float*)d_in[11];
    const float* ln2_w = (const float*)d_in[12];
    const float* ln2_b = (const float*)d_in[13];
    const float* fc1_w = (const float*)d_in[14];
    const float* fc1_b = (const float*)d_in[15];
    const float* fc2_w = (const float*)d_in[16];
    const float* fc2_b = (const float*)d_in[17];
    const float* lam2  = (const float*)d_in[18];
    float* out = (float*)d_out;

    __nv_bfloat16 *wqkv_hi, *wqkv_lo, *wo_hi, *wo_lo, *wf1_hi, *wf1_lo, *wf2_hi, *wf2_lo;
    __nv_bfloat16 *xn_hi, *xn_lo, *qkv_hi, *qkv_lo, *ctx_hi, *ctx_lo, *y2_hi, *y2_lo, *h1_hi, *h1_lo;
    float *qkvb, *hid;
    cudaGetSymbolAddress((void**)&wqkv_hi, g_wqkv_hi);
    cudaGetSymbolAddress((void**)&wqkv_lo, g_wqkv_lo);
    cudaGetSymbolAddress((void**)&wo_hi,   g_wo_hi);
    cudaGetSymbolAddress((void**)&wo_lo,   g_wo_lo);
    cudaGetSymbolAddress((void**)&wf1_hi,  g_wf1_hi);
    cudaGetSymbolAddress((void**)&wf1_lo,  g_wf1_lo);
    cudaGetSymbolAddress((void**)&wf2_hi,  g_wf2_hi);
    cudaGetSymbolAddress((void**)&wf2_lo,  g_wf2_lo);
    cudaGetSymbolAddress((void**)&qkvb,    g_qkvb);
    cudaGetSymbolAddress((void**)&xn_hi,   g_xn_hi);
    cudaGetSymbolAddress((void**)&xn_lo,   g_xn_lo);
    cudaGetSymbolAddress((void**)&qkv_hi,  g_qkv_hi);
    cudaGetSymbolAddress((void**)&qkv_lo,  g_qkv_lo);
    cudaGetSymbolAddress((void**)&ctx_hi,  g_ctx_hi);
    cudaGetSymbolAddress((void**)&ctx_lo,  g_ctx_lo);
    cudaGetSymbolAddress((void**)&hid,     g_hid);
    cudaGetSymbolAddress((void**)&y2_hi,   g_y2_hi);
    cudaGetSymbolAddress((void**)&y2_lo,   g_y2_lo);
    cudaGetSymbolAddress((void**)&h1_hi,   g_h1_hi);
    cudaGetSymbolAddress((void**)&h1_lo,   g_h1_lo);

    // ---- weight prep ----
    dim3 tb(32, 8);
    wsplit<<<dim3(CDIM / 32, CDIM / 32), tb>>>(q_w, CDIM, CDIM, wqkv_hi, wqkv_lo);
    wsplit<<<dim3(CDIM / 32, CDIM / 32), tb>>>(k_w, CDIM, CDIM, wqkv_hi + CDIM * CDIM, wqkv_lo + CDIM * CDIM);
    wsplit<<<dim3(CDIM / 32, CDIM / 32), tb>>>(v_w, CDIM, CDIM, wqkv_hi + 2 * CDIM * CDIM, wqkv_lo + 2 * CDIM * CDIM);
    wsplit<<<dim3(CDIM / 32, CDIM / 32), tb>>>(o_w, CDIM, CDIM, wo_hi, wo_lo);
    wsplit<<<dim3(FDIM / 32, CDIM / 32), tb>>>(fc1_w, CDIM, FDIM, wf1_hi, wf1_lo);
    wsplit<<<dim3(CDIM / 32, FDIM / 32), tb>>>(fc2_w, FDIM, CDIM, wf2_hi, wf2_lo);
    catbias<<<9, 256>>>(q_b, k_b, v_b, qkvb);

    cudaFuncSetAttribute(mmagemm<0>, cudaFuncAttributeMaxDynamicSharedMemorySize, GEMM_SMEM);
    cudaFuncSetAttribute(mmagemm<1>, cudaFuncAttributeMaxDynamicSharedMemorySize, GEMM_SMEM);
    cudaFuncSetAttribute(mmagemm<2>, cudaFuncAttributeMaxDynamicSharedMemorySize, GEMM_SMEM);
    cudaFuncSetAttribute(mmagemm<3>, cudaFuncAttributeMaxDynamicSharedMemorySize, GEMM_SMEM);
    cudaFuncSetAttribute(attn_mma,   cudaFuncAttributeMaxDynamicSharedMemorySize, ATT_SMEM);

    // 1) LN1 -> bf16 split
    ln_split<<<TOK, 256>>>(hs, ln1_w, ln1_b, xn_hi, xn_lo);

    // 2) fused QKV -> bf16 hi/lo [8192, 2304]
    mmagemm<3><<<dim3(QKVC / 128, TOK / 128), 256, GEMM_SMEM>>>(
        xn_hi, xn_lo, wqkv_hi, wqkv_lo, qkvb, TOK, QKVC, CDIM,
        nullptr, qkv_hi, qkv_lo, nullptr, nullptr);

    // 3) attention (tensor cores) -> ctx hi/lo
    attn_mma<<<dim3(SS / 64, HH, BB), 128, ATT_SMEM>>>(qkv_hi, qkv_lo, ctx_hi, ctx_lo);

    // 4) O projection + lam1*. + shortcut -> hid fp32
    mmagemm<1><<<dim3(CDIM / 128, TOK / 128), 256, GEMM_SMEM>>>(
        ctx_hi, ctx_lo, wo_hi, wo_lo, o_b, TOK, CDIM, CDIM,
        hid, nullptr, nullptr, lam1, hs);

    // 5) LN2 -> bf16 split
    ln_split<<<TOK, 256>>>(hid, ln2_w, ln2_b, y2_hi, y2_lo);

    // 6) FC1 + exact GELU -> h1 hi/lo
    mmagemm<2><<<dim3(FDIM / 128, TOK / 128), 256, GEMM_SMEM>>>(
        y2_hi, y2_lo, wf1_hi, wf1_lo, fc1_b, TOK, FDIM, CDIM,
        nullptr, h1_hi, h1_lo, nullptr, nullptr);

    // 7) FC2 + lam2*. + hid -> out fp32
    mmagemm<1><<<dim3(CDIM / 128, TOK / 128), 256, GEMM_SMEM>>>(
        h1_hi, h1_lo, wf2_hi, wf2_lo, fc2_b, TOK, CDIM, FDIM,
        out, nullptr, nullptr, lam2, hid);
}

// round 6
// speedup vs baseline: 2.9513x; 1.0234x over previous
#include <cuda_runtime.h>
#include <cuda_bf16.h>
#include <math.h>
#include <cstdint>

// Problem constants
#define TOK   8192      // B*S
#define CDIM  768
#define FDIM  3072
#define QKVC  2304      // 3*C
#define BB    8
#define SS    1024
#define HH    12
#define DD    64

// ===========================================================================
// Scratch (device globals -- no allocation allowed)
// ===========================================================================
__device__ __nv_bfloat16 g_wqkv_hi[QKVC * CDIM];   // [N,K]
__device__ __nv_bfloat16 g_wqkv_lo[QKVC * CDIM];
__device__ __nv_bfloat16 g_wo_hi  [CDIM * CDIM];
__device__ __nv_bfloat16 g_wo_lo  [CDIM * CDIM];
__device__ __nv_bfloat16 g_wf1_hi [FDIM * CDIM];
__device__ __nv_bfloat16 g_wf1_lo [FDIM * CDIM];
__device__ __nv_bfloat16 g_wf2_hi [CDIM * FDIM];
__device__ __nv_bfloat16 g_wf2_lo [CDIM * FDIM];
__device__ float         g_qkvb  [QKVC];
__device__ __nv_bfloat16 g_xn_hi [TOK * CDIM];
__device__ __nv_bfloat16 g_xn_lo [TOK * CDIM];
__device__ __nv_bfloat16 g_qkv_hi[TOK * QKVC];
__device__ __nv_bfloat16 g_qkv_lo[TOK * QKVC];
__device__ __nv_bfloat16 g_ctx_hi[TOK * CDIM];
__device__ __nv_bfloat16 g_ctx_lo[TOK * CDIM];
__device__ float         g_hid   [TOK * CDIM];
__device__ __nv_bfloat16 g_y2_hi [TOK * CDIM];
__device__ __nv_bfloat16 g_y2_lo [TOK * CDIM];
__device__ __nv_bfloat16 g_h1_hi [TOK * FDIM];
__device__ __nv_bfloat16 g_h1_lo [TOK * FDIM];

// ===========================================================================
// PTX helpers (base ISA only)
// ===========================================================================
__device__ __forceinline__ uint32_t smem_u32(const void* p) {
    uint32_t a;
    asm("{ .reg .u64 t; cvta.to.shared.u64 t, %1; cvt.u32.u64 %0, t; }"
        : "=r"(a) : "l"(p));
    return a;
}
__device__ __forceinline__ void cp_async16(uint32_t s, const void* g) {
    asm volatile("cp.async.cg.shared.global [%0], [%1], 16;" :: "r"(s), "l"(g));
}
#define CP_COMMIT() asm volatile("cp.async.commit_group;")
#define CP_WAIT2()  asm volatile("cp.async.wait_group 2;")
#define CP_WAIT1()  asm volatile("cp.async.wait_group 1;")
#define CP_WAIT0()  asm volatile("cp.async.wait_group 0;")

__device__ __forceinline__ void ldm_x4(uint32_t* r, uint32_t addr) {
    asm volatile("ldmatrix.sync.aligned.m8n8.x4.shared.b16 {%0,%1,%2,%3}, [%4];"
        : "=r"(r[0]), "=r"(r[1]), "=r"(r[2]), "=r"(r[3]) : "r"(addr));
}
__device__ __forceinline__ void ldm_x4t(uint32_t* r, uint32_t addr) {
    asm volatile("ldmatrix.sync.aligned.m8n8.x4.trans.shared.b16 {%0,%1,%2,%3}, [%4];"
        : "=r"(r[0]), "=r"(r[1]), "=r"(r[2]), "=r"(r[3]) : "r"(addr));
}

// D += A @ B  (m16n8k16, bf16 inputs, f32 accum)
__device__ __forceinline__ void mma_bf16(float* c, const uint32_t* a, const uint32_t* b) {
    asm volatile(
        "mma.sync.aligned.m16n8k16.row.col.f32.bf16.bf16.f32 "
        "{%0,%1,%2,%3}, {%4,%5,%6,%7}, {%8,%9}, {%0,%1,%2,%3};"
        : "+f"(c[0]), "+f"(c[1]), "+f"(c[2]), "+f"(c[3])
        : "r"(a[0]), "r"(a[1]), "r"(a[2]), "r"(a[3]), "r"(b[0]), "r"(b[1]));
}

__device__ __forceinline__ void split1(float x, __nv_bfloat16& h, __nv_bfloat16& l) {
    h = __float2bfloat16_rn(x);
    l = __float2bfloat16_rn(x - __bfloat162float(h));
}
__device__ __forceinline__ void split_pack(float x, float y, uint32_t& hi, uint32_t& lo) {
    __nv_bfloat16 hx, lx, hy, ly;
    split1(x, hx, lx); split1(y, hy, ly);
    __nv_bfloat162 hp; hp.x = hx; hp.y = hy;
    __nv_bfloat162 lp; lp.x = lx; lp.y = ly;
    hi = *(uint32_t*)&hp; lo = *(uint32_t*)&lp;
}

// ===========================================================================
// Fused weight transpose + split (ALL matrices, single launch):
// W[K,N] fp32 -> hi/lo[N,K] bf16, 32x32 tiles, linearized grid.
// ===========================================================================
#define WS_BLOCKS 6912   // 4*576 + 2304 + 2304

__global__ __launch_bounds__(256) void wsplit_all(
    const float* __restrict__ qw, const float* __restrict__ kw,
    const float* __restrict__ vw, const float* __restrict__ ow,
    const float* __restrict__ f1, const float* __restrict__ f2,
    __nv_bfloat16* __restrict__ wqkv_hi, __nv_bfloat16* __restrict__ wqkv_lo,
    __nv_bfloat16* __restrict__ wo_hi,   __nv_bfloat16* __restrict__ wo_lo,
    __nv_bfloat16* __restrict__ wf1_hi,  __nv_bfloat16* __restrict__ wf1_lo,
    __nv_bfloat16* __restrict__ wf2_hi,  __nv_bfloat16* __restrict__ wf2_lo)
{
    int id = blockIdx.x;
    const float* W; __nv_bfloat16 *hi, *lo;
    int K, N;
    if (id < 2304) {            // q, k, v, o : 24x24 = 576 blocks each
        int seg = id / 576, loc = id % 576;
        K = CDIM; N = CDIM;
        if (seg == 0)      { W = qw; hi = wqkv_hi;                 lo = wqkv_lo; }
        else if (seg == 1) { W = kw; hi = wqkv_hi + CDIM * CDIM;   lo = wqkv_lo + CDIM * CDIM; }
        else if (seg == 2) { W = vw; hi = wqkv_hi + 2*CDIM*CDIM;   lo = wqkv_lo + 2*CDIM*CDIM; }
        else               { W = ow; hi = wo_hi;                    lo = wo_lo; }
        id = loc;
    } else if (id < 4608) {     // fc1: K=768, N=3072 -> 96x24
        id -= 2304; K = CDIM; N = FDIM; W = f1; hi = wf1_hi; lo = wf1_lo;
    } else {                    // fc2: K=3072, N=768 -> 24x96
        id -= 4608; K = FDIM; N = CDIM; W = f2; hi = wf2_hi; lo = wf2_lo;
    }
    const int nb = N / 32;
    const int n0 = (id % nb) * 32, k0 = (id / nb) * 32;

    __shared__ float t[32][33];
    const int tx = threadIdx.x & 31, ty = threadIdx.x >> 5;   // 32 x 8
    #pragma unroll
    for (int i = 0; i < 32; i += 8)
        t[ty + i][tx] = W[(size_t)(k0 + ty + i) * N + n0 + tx];
    __syncthreads();
    #pragma unroll
    for (int i = 0; i < 32; i += 8) {
        float v = t[tx][ty + i];
        __nv_bfloat16 h, l; split1(v, h, l);
        size_t o = (size_t)(n0 + ty + i) * K + k0 + tx;
        hi[o] = h; lo[o] = l;
    }
}

__global__ void catbias(const float* __restrict__ qb, const float* __restrict__ kb,
                        const float* __restrict__ vb, float* __restrict__ out)
{
    int i = blockIdx.x * blockDim.x + threadIdx.x;
    if (i < CDIM)            out[i] = qb[i];
    else if (i < 2 * CDIM)   out[i] = kb[i - CDIM];
    else if (i < 3 * CDIM)   out[i] = vb[i - 2 * CDIM];
}

// ===========================================================================
// LayerNorm -> bf16 hi/lo. Warp-per-row (8 rows / 256-thread block).
// ===========================================================================
__global__ __launch_bounds__(256) void ln_split(
    const float* __restrict__ x, const float* __restrict__ w,
    const float* __restrict__ b,
    __nv_bfloat16* __restrict__ hi, __nv_bfloat16* __restrict__ lo)
{
    const int row  = blockIdx.x * 8 + (threadIdx.x >> 5);
    const int lane = threadIdx.x & 31;
    const float* xr = x + (size_t)row * CDIM;

    float4 v[6];
    float s = 0.f, s2 = 0.f;
    #pragma unroll
    for (int i = 0; i < 6; i++) {
        v[i] = *(const float4*)(xr + i * 128 + lane * 4);
        s  += v[i].x + v[i].y + v[i].z + v[i].w;
        s2 += v[i].x*v[i].x + v[i].y*v[i].y + v[i].z*v[i].z + v[i].w*v[i].w;
    }
    #pragma unroll
    for (int o = 16; o > 0; o >>= 1) {
        s  += __shfl_xor_sync(0xffffffffu, s,  o);
        s2 += __shfl_xor_sync(0xffffffffu, s2, o);
    }
    const float mu  = s * (1.0f / CDIM);
    const float var = s2 * (1.0f / CDIM) - mu * mu;
    const float inv = rsqrtf(var + 1e-6f);

    size_t ro = (size_t)row * CDIM;
    #pragma unroll
    for (int i = 0; i < 6; i++) {
        int c = i * 128 + lane * 4;
        float4 wv = *(const float4*)(w + c);
        float4 bv = *(const float4*)(b + c);
        float y0 = (v[i].x - mu) * inv * wv.x + bv.x;
        float y1 = (v[i].y - mu) * inv * wv.y + bv.y;
        float y2 = (v[i].z - mu) * inv * wv.z + bv.z;
        float y3 = (v[i].w - mu) * inv * wv.w + bv.w;
        uint32_t h01, l01, h23, l23;
        split_pack(y0, y1, h01, l01);
        split_pack(y2, y3, h23, l23);
        *(uint2*)(hi + ro + c) = make_uint2(h01, h23);
        *(uint2*)(lo + ro + c) = make_uint2(l01, l23);
    }
}

// ===========================================================================
// bf16-split tensor GEMM via ldmatrix + mma.sync, 3-stage cp.async pipeline.
// C[M,N] = A @ B^T ; A,B given as hi/lo bf16 [rows,K].
// 128x128 CTA tile, BK=64, 256 threads (8 warps).
// EPI 0: +bias -> fp32 ; EPI 1: (+bias)*lam+res -> fp32 ;
// EPI 2: gelu_exact(+bias) -> bf16 hi/lo ; EPI 3: +bias -> bf16 hi/lo
// ===========================================================================
#define RSB   144                       // bytes per smem row (128 + 16 pad)
#define TILEB (128 * RSB)               // 18432 bytes per tile
#define GEMM_SMEM (12 * TILEB)          // 3 stages x 4 tiles = 221184

template<int EPI>
__global__ __launch_bounds__(256) void mmagemm(
    const __nv_bfloat16* __restrict__ Ahi, const __nv_bfloat16* __restrict__ Alo,
    const __nv_bfloat16* __restrict__ Bhi, const __nv_bfloat16* __restrict__ Blo,
    const float* __restrict__ bias,
    int M, int N, int K,
    float* __restrict__ Cf,
    __nv_bfloat16* __restrict__ Chi, __nv_bfloat16* __restrict__ Clo,
    const float* __restrict__ lam, const float* __restrict__ res)
{
    extern __shared__ char smc[];
    const uint32_t sb = smem_u32(smc);

    const int tid  = threadIdx.x;
    const int wid  = tid >> 5;
    const int lane = tid & 31;
    const int wm   = wid & 1;
    const int wn   = wid >> 1;
    const int m0   = blockIdx.y * 128;
    const int n0   = blockIdx.x * 128;

    auto load_tile = [&](const __nv_bfloat16* __restrict__ G, int row0, int k0,
                         uint32_t dst) {
        #pragma unroll
        for (int i = 0; i < 4; i++) {
            int idx = tid + (i << 8);
            int r   = idx >> 3;
            int cc  = idx & 7;
            cp_async16(dst + r * RSB + cc * 16,
                       G + (size_t)(row0 + r) * K + k0 + cc * 8);
        }
    };
    auto load_chunk = [&](int k0, int p) {
        uint32_t base = sb + (uint32_t)p * (4 * TILEB);
        load_tile(Ahi, m0, k0, base);
        load_tile(Alo, m0, k0, base + TILEB);
        load_tile(Bhi, n0, k0, base + 2 * TILEB);
        load_tile(Blo, n0, k0, base + 3 * TILEB);
        CP_COMMIT();
    };

    float acc[4][4][4];
    #pragma unroll
    for (int t = 0; t < 4; t++)
        #pragma unroll
        for (int u = 0; u < 4; u++)
            #pragma unroll
            for (int e = 0; e < 4; e++) acc[t][u][e] = 0.f;

    const int nch = K >> 6;   // BK = 64 ; nch is 12 or 48
    load_chunk(0, 0);
    load_chunk(64, 1);
    load_chunk(128, 2);

    const int aRow = (lane & 7) + ((lane >> 3) & 1) * 8;
    const int aCol = (lane >> 4) * 16;
    const int bRow = (lane & 7) + (lane >> 4) * 8;
    const int bCol = ((lane >> 3) & 1) * 16;

    for (int it = 0; it < nch; ++it) {
        const int p = it % 3;
        if (it + 3 <= nch)      { CP_WAIT2(); }
        else if (it + 2 <= nch) { CP_WAIT1(); }
        else                    { CP_WAIT0(); }
        __syncthreads();

        const uint32_t base = sb + (uint32_t)p * (4 * TILEB);
        const uint32_t sAh = base;
        const uint32_t sAl = base + TILEB;
        const uint32_t sBh = base + 2 * TILEB;
        const uint32_t sBl = base + 3 * TILEB;

        #pragma unroll
        for (int ks = 0; ks < 4; ks++) {
            const int kb = ks * 32;
            uint32_t ah[4][4], al[4][4];
            #pragma unroll
            for (int t = 0; t < 4; t++) {
                uint32_t ro = (uint32_t)((wm * 64 + t * 16 + aRow) * RSB + kb + aCol);
                ldm_x4(ah[t], sAh + ro);
                ldm_x4(al[t], sAl + ro);
            }
            uint32_t bh[2][4];
            #pragma unroll
            for (int u2 = 0; u2 < 2; u2++) {
                uint32_t ro = (uint32_t)((wn * 32 + u2 * 16 + bRow) * RSB + kb + bCol);
                ldm_x4(bh[u2], sBh + ro);
            }
            #pragma unroll
            for (int t = 0; t < 4; t++)
                #pragma unroll
                for (int u = 0; u < 4; u++) {
                    mma_bf16(acc[t][u], ah[t], &bh[u >> 1][(u & 1) * 2]);
                    mma_bf16(acc[t][u], al[t], &bh[u >> 1][(u & 1) * 2]);
                }
            uint32_t bl[2][4];
            #pragma unroll
            for (int u2 = 0; u2 < 2; u2++) {
                uint32_t ro = (uint32_t)((wn * 32 + u2 * 16 + bRow) * RSB + kb + bCol);
                ldm_x4(bl[u2], sBl + ro);
            }
            #pragma unroll
            for (int t = 0; t < 4; t++)
                #pragma unroll
                for (int u = 0; u < 4; u++)
                    mma_bf16(acc[t][u], ah[t], &bl[u >> 1][(u & 1) * 2]);
        }
        __syncthreads();
        if (it + 3 < nch) load_chunk((it + 3) << 6, p);
    }

    #pragma unroll
    for (int t = 0; t < 4; t++) {
        const int rbase = m0 + wm * 64 + t * 16 + (lane >> 2);
        #pragma unroll
        for (int u = 0; u < 4; u++) {
            const int c = n0 + wn * 32 + u * 8 + (lane & 3) * 2;
            #pragma unroll
            for (int half = 0; half < 2; half++) {
                const int r = rbase + half * 8;
                const size_t ro = (size_t)r * N;
                float v0 = acc[t][u][half * 2 + 0] + bias[c];
                float v1 = acc[t][u][half * 2 + 1] + bias[c + 1];
                if (EPI == 1) {
                    v0 = v0 * lam[c]     + res[ro + c];
                    v1 = v1 * lam[c + 1] + res[ro + c + 1];
                    *(float2*)(Cf + ro + c) = make_float2(v0, v1);
                } else if (EPI == 2 || EPI == 3) {
                    if (EPI == 2) {
                        v0 = 0.5f * v0 * (1.0f + erff(v0 * 0.70710678118654752f));
                        v1 = 0.5f * v1 * (1.0f + erff(v1 * 0.70710678118654752f));
                    }
                    uint32_t hp, lp;
                    split_pack(v0, v1, hp, lp);
                    *(uint32_t*)(Chi + ro + c) = hp;
                    *(uint32_t*)(Clo + ro + c) = lp;
                } else {
                    *(float2*)(Cf + ro + c) = make_float2(v0, v1);
                }
            }
        }
    }
}

// ===========================================================================
// Flash attention on tensor cores (bf16-split, online softmax).
// Inputs: qkv hi/lo bf16 [tok, 2304]; output ctx hi/lo bf16 [tok, 768].
// Grid: (S/64, H, B), 128 threads (4 warps x m16 q-rows). BN = 64 keys/iter.
// ===========================================================================
#define AT_Q    0
#define AT_BUF  18432
#define AT_TILE 9216
#define ATT_SMEM (18432 + 2 * 4 * 9216)  // 92160

__global__ __launch_bounds__(128) void attn_mma(
    const __nv_bfloat16* __restrict__ qhi, const __nv_bfloat16* __restrict__ qlo,
    __nv_bfloat16* __restrict__ chi, __nv_bfloat16* __restrict__ clo)
{
    extern __shared__ char smc[];
    const uint32_t sb = smem_u32(smc);
    const int tid  = threadIdx.x;
    const int wid  = tid >> 5;
    const int lane = tid & 31;
    const int h    = blockIdx.y;
    const int b    = blockIdx.z;
    const int q0   = blockIdx.x * 64;

    for (int i = tid; i < 512; i += 128) {
        int r = i >> 3, c = i & 7;
        size_t g = (size_t)(b * SS + q0 + r) * QKVC + h * DD + c * 8;
        cp_async16(sb + AT_Q + r * RSB + c * 16, qhi + g);
        cp_async16(sb + AT_Q + AT_TILE + r * RSB + c * 16, qlo + g);
    }
    CP_COMMIT();

    auto load_kv = [&](int j0, int p) {
        uint32_t base = sb + AT_BUF + (uint32_t)p * (4 * AT_TILE);
        for (int i = tid; i < 512; i += 128) {
            int r = i >> 3, c = i & 7;
            size_t gk = (size_t)(b * SS + j0 + r) * QKVC + CDIM + h * DD + c * 8;
            size_t gv = gk + CDIM;
            cp_async16(base + r * RSB + c * 16,                qhi + gk);
            cp_async16(base + AT_TILE + r * RSB + c * 16,      qlo + gk);
            cp_async16(base + 2 * AT_TILE + r * RSB + c * 16,  qhi + gv);
            cp_async16(base + 3 * AT_TILE + r * RSB + c * 16,  qlo + gv);
        }
        CP_COMMIT();
    };
    load_kv(0, 0);
    load_kv(64, 1);

    const int aRow = (lane & 7) + ((lane >> 3) & 1) * 8;
    const int aCol = (lane >> 4) * 16;
    const int bRow = (lane & 7) + (lane >> 4) * 8;
    const int bCol = ((lane >> 3) & 1) * 16;
    const int vRow = (lane & 7) + ((lane >> 3) & 1) * 8;
    const int vCol = (lane >> 4) * 16;

    CP_WAIT2();
    __syncthreads();

    uint32_t qh[4][4], ql[4][4];
    #pragma unroll
    for (int ks = 0; ks < 4; ks++) {
        uint32_t ro = (uint32_t)((wid * 16 + aRow) * RSB + ks * 32 + aCol);
        ldm_x4(qh[ks], sb + AT_Q + ro);
        ldm_x4(ql[ks], sb + AT_Q + AT_TILE + ro);
    }

    float oacc[8][4];
    #pragma unroll
    for (int u = 0; u < 8; u++)
        #pragma unroll
        for (int e = 0; e < 4; e++) oacc[u][e] = 0.f;
    float m0 = -1e30f, m1 = -1e30f, l0 = 0.f, l1 = 0.f;

    const int nt = SS / 64;   // 16
    for (int it = 0; it < nt; ++it) {
        const int p = it & 1;
        if (it + 1 < nt) { CP_WAIT1(); } else { CP_WAIT0(); }
        __syncthreads();

        const uint32_t base = sb + AT_BUF + (uint32_t)p * (4 * AT_TILE);
        const uint32_t sKh = base;
        const uint32_t sKl = base + AT_TILE;
        const uint32_t sVh = base + 2 * AT_TILE;
        const uint32_t sVl = base + 3 * AT_TILE;

        float sacc[8][4];
        #pragma unroll
        for (int u = 0; u < 8; u++)
            #pragma unroll
            for (int e = 0; e < 4; e++) sacc[u][e] = 0.f;

        #pragma unroll
        for (int ks = 0; ks < 4; ks++) {
            const int kb = ks * 32;
            uint32_t kh[4][4], kl[4][4];
            #pragma unroll
            for (int g = 0; g < 4; g++) {
                uint32_t ro = (uint32_t)((g * 16 + bRow) * RSB + kb + bCol);
                ldm_x4(kh[g], sKh + ro);
                ldm_x4(kl[g], sKl + ro);
            }
            #pragma unroll
            for (int g = 0; g < 4; g++)
                #pragma unroll
                for (int hf = 0; hf < 2; hf++) {
                    int u = g * 2 + hf;
                    mma_bf16(sacc[u], qh[ks], &kh[g][hf * 2]);
                    mma_bf16(sacc[u], ql[ks], &kh[g][hf * 2]);
                    mma_bf16(sacc[u], qh[ks], &kl[g][hf * 2]);
                }
        }

        float mx0 = m0, mx1 = m1;
        #pragma unroll
        for (int u = 0; u < 8; u++) {
            sacc[u][0] *= 0.125f; sacc[u][1] *= 0.125f;
            sacc[u][2] *= 0.125f; sacc[u][3] *= 0.125f;
            mx0 = fmaxf(mx0, fmaxf(sacc[u][0], sacc[u][1]));
            mx1 = fmaxf(mx1, fmaxf(sacc[u][2], sacc[u][3]));
        }
        mx0 = fmaxf(mx0, __shfl_xor_sync(0xffffffffu, mx0, 1));
        mx0 = fmaxf(mx0, __shfl_xor_sync(0xffffffffu, mx0, 2));
        mx1 = fmaxf(mx1, __shfl_xor_sync(0xffffffffu, mx1, 1));
        mx1 = fmaxf(mx1, __shfl_xor_sync(0xffffffffu, mx1, 2));
        float al0 = __expf(m0 - mx0), al1 = __expf(m1 - mx1);
        m0 = mx0; m1 = mx1;
        float sum0 = 0.f, sum1 = 0.f;
        #pragma unroll
        for (int u = 0; u < 8; u++) {
            sacc[u][0] = __expf(sacc[u][0] - m0);
            sacc[u][1] = __expf(sacc[u][1] - m0);
            sacc[u][2] = __expf(sacc[u][2] - m1);
            sacc[u][3] = __expf(sacc[u][3] - m1);
            sum0 += sacc[u][0] + sacc[u][1];
            sum1 += sacc[u][2] + sacc[u][3];
        }
        sum0 += __shfl_xor_sync(0xffffffffu, sum0, 1);
        sum0 += __shfl_xor_sync(0xffffffffu, sum0, 2);
        sum1 += __shfl_xor_sync(0xffffffffu, sum1, 1);
        sum1 += __shfl_xor_sync(0xffffffffu, sum1, 2);
        l0 = l0 * al0 + sum0;
        l1 = l1 * al1 + sum1;
        #pragma unroll
        for (int u = 0; u < 8; u++) {
            oacc[u][0] *= al0; oacc[u][1] *= al0;
            oacc[u][2] *= al1; oacc[u][3] *= al1;
        }

        uint32_t ph[4][4], pl[4][4];
        #pragma unroll
        for (int t = 0; t < 4; t++) {
            split_pack(sacc[2*t][0],   sacc[2*t][1],   ph[t][0], pl[t][0]);
            split_pack(sacc[2*t][2],   sacc[2*t][3],   ph[t][1], pl[t][1]);
            split_pack(sacc[2*t+1][0], sacc[2*t+1][1], ph[t][2], pl[t][2]);
            split_pack(sacc[2*t+1][2], sacc[2*t+1][3], ph[t][3], pl[t][3]);
        }

        #pragma unroll
        for (int t = 0; t < 4; t++) {
            uint32_t vh[4][4], vl[4][4];
            #pragma unroll
            for (int g = 0; g < 4; g++) {
                uint32_t ro = (uint32_t)((t * 16 + vRow) * RSB + g * 32 + vCol);
                ldm_x4t(vh[g], sVh + ro);
                ldm_x4t(vl[g], sVl + ro);
            }
            #pragma unroll
            for (int g = 0; g < 4; g++)
                #pragma unroll
                for (int hf = 0; hf < 2; hf++) {
                    int u = g * 2 + hf;
                    mma_bf16(oacc[u], ph[t], &vh[g][hf * 2]);
                    mma_bf16(oacc[u], pl[t], &vh[g][hf * 2]);
                    mma_bf16(oacc[u], ph[t], &vl[g][hf * 2]);
                }
        }

        __syncthreads();
        if (it + 2 < nt) load_kv((it + 2) * 64, p);
    }

    float inv0 = 1.0f / l0, inv1 = 1.0f / l1;
    const int r  = lane >> 2;
    const int cc = (lane & 3) * 2;
    #pragma unroll
    for (int u = 0; u < 8; u++) {
        int col = h * DD + u * 8 + cc;
        size_t o0 = (size_t)(b * SS + q0 + wid * 16 + r)     * CDIM + col;
        size_t o1 = (size_t)(b * SS + q0 + wid * 16 + r + 8) * CDIM + col;
        uint32_t hp, lp;
        split_pack(oacc[u][0] * inv0, oacc[u][1] * inv0, hp, lp);
        *(uint32_t*)(chi + o0) = hp;
        *(uint32_t*)(clo + o0) = lp;
        split_pack(oacc[u][2] * inv1, oacc[u][3] * inv1, hp, lp);
        *(uint32_t*)(chi + o1) = hp;
        *(uint32_t*)(clo + o1) = lp;
    }
}

// ===========================================================================
// Launch
// ===========================================================================
extern "C" void kernel_launch(void* const* d_in, const int* in_sizes, int n_in,
                              void* d_out, int out_size)
{
    const float* hs    = (const float*)d_in[0];
    const float* ln1_w = (const float*)d_in[1];
    const float* ln1_b = (const float*)d_in[2];
    const float* q_w   = (const float*)d_in[3];
    const float* q_b   = (const float*)d_in[4];
    const float* k_w   = (const float*)d_in[5];
    const float* k_b   = (const float*)d_in[6];
    const float* v_w   = (const float*)d_in[7];
    const float* v_b   = (const float*)d_in[8];
    const float* o_w   = (const float*)d_in[9];
    const float* o_b   = (const float*)d_in[10];
    const float* lam1  = (const float*)d_in[11];
    const float* ln2_w = (const float*)d_in[12];
    const float* ln2_b = (const float*)d_in[13];
    const float* fc1_w = (const float*)d_in[14];
    const float* fc1_b = (const float*)d_in[15];
    const float* fc2_w = (const float*)d_in[16];
    const float* fc2_b = (const float*)d_in[17];
    const float* lam2  = (const float*)d_in[18];
    float* out = (float*)d_out;

    __nv_bfloat16 *wqkv_hi, *wqkv_lo, *wo_hi, *wo_lo, *wf1_hi, *wf1_lo, *wf2_hi, *wf2_lo;
    __nv_bfloat16 *xn_hi, *xn_lo, *qkv_hi, *qkv_lo, *ctx_hi, *ctx_lo, *y2_hi, *y2_lo, *h1_hi, *h1_lo;
    float *qkvb, *hid;
    cudaGetSymbolAddress((void**)&wqkv_hi, g_wqkv_hi);
    cudaGetSymbolAddress((void**)&wqkv_lo, g_wqkv_lo);
    cudaGetSymbolAddress((void**)&wo_hi,   g_wo_hi);
    cudaGetSymbolAddress((void**)&wo_lo,   g_wo_lo);
    cudaGetSymbolAddress((void**)&wf1_hi,  g_wf1_hi);
    cudaGetSymbolAddress((void**)&wf1_lo,  g_wf1_lo);
    cudaGetSymbolAddress((void**)&wf2_hi,  g_wf2_hi);
    cudaGetSymbolAddress((void**)&wf2_lo,  g_wf2_lo);
    cudaGetSymbolAddress((void**)&qkvb,    g_qkvb);
    cudaGetSymbolAddress((void**)&xn_hi,   g_xn_hi);
    cudaGetSymbolAddress((void**)&xn_lo,   g_xn_lo);
    cudaGetSymbolAddress((void**)&qkv_hi,  g_qkv_hi);
    cudaGetSymbolAddress((void**)&qkv_lo,  g_qkv_lo);
    cudaGetSymbolAddress((void**)&ctx_hi,  g_ctx_hi);
    cudaGetSymbolAddress((void**)&ctx_lo,  g_ctx_lo);
    cudaGetSymbolAddress((void**)&hid,     g_hid);
    cudaGetSymbolAddress((void**)&y2_hi,   g_y2_hi);
    cudaGetSymbolAddress((void**)&y2_lo,   g_y2_lo);
    cudaGetSymbolAddress((void**)&h1_hi,   g_h1_hi);
    cudaGetSymbolAddress((void**)&h1_lo,   g_h1_lo);

    // 1) weight prep (single launch) + bias concat
    wsplit_all<<<WS_BLOCKS, 256>>>(q_w, k_w, v_w, o_w, fc1_w, fc2_w,
                                   wqkv_hi, wqkv_lo, wo_hi, wo_lo,
                                   wf1_hi, wf1_lo, wf2_hi, wf2_lo);
    catbias<<<9, 256>>>(q_b, k_b, v_b, qkvb);

    cudaFuncSetAttribute(mmagemm<0>, cudaFuncAttributeMaxDynamicSharedMemorySize, GEMM_SMEM);
    cudaFuncSetAttribute(mmagemm<1>, cudaFuncAttributeMaxDynamicSharedMemorySize, GEMM_SMEM);
    cudaFuncSetAttribute(mmagemm<2>, cudaFuncAttributeMaxDynamicSharedMemorySize, GEMM_SMEM);
    cudaFuncSetAttribute(mmagemm<3>, cudaFuncAttributeMaxDynamicSharedMemorySize, GEMM_SMEM);
    cudaFuncSetAttribute(attn_mma,   cudaFuncAttributeMaxDynamicSharedMemorySize, ATT_SMEM);

    // 2) LN1 -> bf16 split
    ln_split<<<TOK / 8, 256>>>(hs, ln1_w, ln1_b, xn_hi, xn_lo);

    // 3) fused QKV -> bf16 hi/lo [8192, 2304]
    mmagemm<3><<<dim3(QKVC / 128, TOK / 128), 256, GEMM_SMEM>>>(
        xn_hi, xn_lo, wqkv_hi, wqkv_lo, qkvb, TOK, QKVC, CDIM,
        nullptr, qkv_hi, qkv_lo, nullptr, nullptr);

    // 4) attention (tensor cores) -> ctx hi/lo
    attn_mma<<<dim3(SS / 64, HH, BB), 128, ATT_SMEM>>>(qkv_hi, qkv_lo, ctx_hi, ctx_lo);

    // 5) O projection + lam1*. + shortcut -> hid fp32   [ncu captures this]
    mmagemm<1><<<dim3(CDIM / 128, TOK / 128), 256, GEMM_SMEM>>>(
        ctx_hi, ctx_lo, wo_hi, wo_lo, o_b, TOK, CDIM, CDIM,
        hid, nullptr, nullptr, lam1, hs);

    // 6) LN2 -> bf16 split
    ln_split<<<TOK / 8, 256>>>(hid, ln2_w, ln2_b, y2_hi, y2_lo);

    // 7) FC1 + exact GELU -> h1 hi/lo
    mmagemm<2><<<dim3(FDIM / 128, TOK / 128), 256, GEMM_SMEM>>>(
        y2_hi, y2_lo, wf1_hi, wf1_lo, fc1_b, TOK, FDIM, CDIM,
        nullptr, h1_hi, h1_lo, nullptr, nullptr);

    // 8) FC2 + lam2*. + hid -> out fp32
    mmagemm<1><<<dim3(CDIM / 128, TOK / 128), 256, GEMM_SMEM>>>(
        h1_hi, h1_lo, wf2_hi, wf2_lo, fc2_b, TOK, CDIM, FDIM,
        out, nullptr, nullptr, lam2, hid);
}

// round 7
// speedup vs baseline: 3.0064x; 1.0187x over previous
#include <cuda_runtime.h>
#include <cuda_bf16.h>
#include <math.h>
#include <cstdint>

// Problem constants
#define TOK   8192      // B*S
#define CDIM  768
#define FDIM  3072
#define QKVC  2304      // 3*C
#define BB    8
#define SS    1024
#define HH    12
#define DD    64

// ===========================================================================
// Scratch (device globals -- no allocation allowed)
// ===========================================================================
__device__ __nv_bfloat16 g_wqkv_hi[QKVC * CDIM];   // [N,K]
__device__ __nv_bfloat16 g_wqkv_lo[QKVC * CDIM];
__device__ __nv_bfloat16 g_wo_hi  [CDIM * CDIM];
__device__ __nv_bfloat16 g_wo_lo  [CDIM * CDIM];
__device__ __nv_bfloat16 g_wf1_hi [FDIM * CDIM];
__device__ __nv_bfloat16 g_wf1_lo [FDIM * CDIM];
__device__ __nv_bfloat16 g_wf2_hi [CDIM * FDIM];
__device__ __nv_bfloat16 g_wf2_lo [CDIM * FDIM];
__device__ float         g_qkvb  [QKVC];
__device__ __nv_bfloat16 g_xn_hi [TOK * CDIM];
__device__ __nv_bfloat16 g_xn_lo [TOK * CDIM];
__device__ __nv_bfloat16 g_qkv_hi[TOK * QKVC];
__device__ __nv_bfloat16 g_qkv_lo[TOK * QKVC];
__device__ __nv_bfloat16 g_ctx_hi[TOK * CDIM];
__device__ __nv_bfloat16 g_ctx_lo[TOK * CDIM];
__device__ float         g_hid   [TOK * CDIM];
__device__ __nv_bfloat16 g_y2_hi [TOK * CDIM];
__device__ __nv_bfloat16 g_y2_lo [TOK * CDIM];
__device__ __nv_bfloat16 g_h1_hi [TOK * FDIM];
__device__ __nv_bfloat16 g_h1_lo [TOK * FDIM];

// ===========================================================================
// PTX helpers (base ISA only)
// ===========================================================================
__device__ __forceinline__ uint32_t smem_u32(const void* p) {
    uint32_t a;
    asm("{ .reg .u64 t; cvta.to.shared.u64 t, %1; cvt.u32.u64 %0, t; }"
        : "=r"(a) : "l"(p));
    return a;
}
__device__ __forceinline__ void cp_async16(uint32_t s, const void* g) {
    asm volatile("cp.async.cg.shared.global [%0], [%1], 16;" :: "r"(s), "l"(g));
}
#define CP_COMMIT() asm volatile("cp.async.commit_group;")
#define CP_WAIT2()  asm volatile("cp.async.wait_group 2;")
#define CP_WAIT1()  asm volatile("cp.async.wait_group 1;")
#define CP_WAIT0()  asm volatile("cp.async.wait_group 0;")

__device__ __forceinline__ void ldm_x4(uint32_t* r, uint32_t addr) {
    asm volatile("ldmatrix.sync.aligned.m8n8.x4.shared.b16 {%0,%1,%2,%3}, [%4];"
        : "=r"(r[0]), "=r"(r[1]), "=r"(r[2]), "=r"(r[3]) : "r"(addr));
}
__device__ __forceinline__ void ldm_x4t(uint32_t* r, uint32_t addr) {
    asm volatile("ldmatrix.sync.aligned.m8n8.x4.trans.shared.b16 {%0,%1,%2,%3}, [%4];"
        : "=r"(r[0]), "=r"(r[1]), "=r"(r[2]), "=r"(r[3]) : "r"(addr));
}

// D += A @ B  (m16n8k16, bf16 inputs, f32 accum)
__device__ __forceinline__ void mma_bf16(float* c, const uint32_t* a, const uint32_t* b) {
    asm volatile(
        "mma.sync.aligned.m16n8k16.row.col.f32.bf16.bf16.f32 "
        "{%0,%1,%2,%3}, {%4,%5,%6,%7}, {%8,%9}, {%0,%1,%2,%3};"
        : "+f"(c[0]), "+f"(c[1]), "+f"(c[2]), "+f"(c[3])
        : "r"(a[0]), "r"(a[1]), "r"(a[2]), "r"(a[3]), "r"(b[0]), "r"(b[1]));
}

__device__ __forceinline__ void split1(float x, __nv_bfloat16& h, __nv_bfloat16& l) {
    h = __float2bfloat16_rn(x);
    l = __float2bfloat16_rn(x - __bfloat162float(h));
}
__device__ __forceinline__ void split_pack(float x, float y, uint32_t& hi, uint32_t& lo) {
    __nv_bfloat16 hx, lx, hy, ly;
    split1(x, hx, lx); split1(y, hy, ly);
    __nv_bfloat162 hp; hp.x = hx; hp.y = hy;
    __nv_bfloat162 lp; lp.x = lx; lp.y = ly;
    hi = *(uint32_t*)&hp; lo = *(uint32_t*)&lp;
}

// ===========================================================================
// Fused weight transpose + split (ALL matrices, single launch)
// ===========================================================================
#define WS_BLOCKS 6912   // 4*576 + 2304 + 2304

__global__ __launch_bounds__(256) void wsplit_all(
    const float* __restrict__ qw, const float* __restrict__ kw,
    const float* __restrict__ vw, const float* __restrict__ ow,
    const float* __restrict__ f1, const float* __restrict__ f2,
    __nv_bfloat16* __restrict__ wqkv_hi, __nv_bfloat16* __restrict__ wqkv_lo,
    __nv_bfloat16* __restrict__ wo_hi,   __nv_bfloat16* __restrict__ wo_lo,
    __nv_bfloat16* __restrict__ wf1_hi,  __nv_bfloat16* __restrict__ wf1_lo,
    __nv_bfloat16* __restrict__ wf2_hi,  __nv_bfloat16* __restrict__ wf2_lo)
{
    int id = blockIdx.x;
    const float* W; __nv_bfloat16 *hi, *lo;
    int K, N;
    if (id < 2304) {
        int seg = id / 576, loc = id % 576;
        K = CDIM; N = CDIM;
        if (seg == 0)      { W = qw; hi = wqkv_hi;                 lo = wqkv_lo; }
        else if (seg == 1) { W = kw; hi = wqkv_hi + CDIM * CDIM;   lo = wqkv_lo + CDIM * CDIM; }
        else if (seg == 2) { W = vw; hi = wqkv_hi + 2*CDIM*CDIM;   lo = wqkv_lo + 2*CDIM*CDIM; }
        else               { W = ow; hi = wo_hi;                    lo = wo_lo; }
        id = loc;
    } else if (id < 4608) {
        id -= 2304; K = CDIM; N = FDIM; W = f1; hi = wf1_hi; lo = wf1_lo;
    } else {
        id -= 4608; K = FDIM; N = CDIM; W = f2; hi = wf2_hi; lo = wf2_lo;
    }
    const int nb = N / 32;
    const int n0 = (id % nb) * 32, k0 = (id / nb) * 32;

    __shared__ float t[32][33];
    const int tx = threadIdx.x & 31, ty = threadIdx.x >> 5;
    #pragma unroll
    for (int i = 0; i < 32; i += 8)
        t[ty + i][tx] = W[(size_t)(k0 + ty + i) * N + n0 + tx];
    __syncthreads();
    #pragma unroll
    for (int i = 0; i < 32; i += 8) {
        float v = t[tx][ty + i];
        __nv_bfloat16 h, l; split1(v, h, l);
        size_t o = (size_t)(n0 + ty + i) * K + k0 + tx;
        hi[o] = h; lo[o] = l;
    }
}

__global__ void catbias(const float* __restrict__ qb, const float* __restrict__ kb,
                        const float* __restrict__ vb, float* __restrict__ out)
{
    int i = blockIdx.x * blockDim.x + threadIdx.x;
    if (i < CDIM)            out[i] = qb[i];
    else if (i < 2 * CDIM)   out[i] = kb[i - CDIM];
    else if (i < 3 * CDIM)   out[i] = vb[i - 2 * CDIM];
}

// ===========================================================================
// LayerNorm -> bf16 hi/lo. Warp-per-row (8 rows / 256-thread block).
// ===========================================================================
__global__ __launch_bounds__(256) void ln_split(
    const float* __restrict__ x, const float* __restrict__ w,
    const float* __restrict__ b,
    __nv_bfloat16* __restrict__ hi, __nv_bfloat16* __restrict__ lo)
{
    const int row  = blockIdx.x * 8 + (threadIdx.x >> 5);
    const int lane = threadIdx.x & 31;
    const float* xr = x + (size_t)row * CDIM;

    float4 v[6];
    float s = 0.f, s2 = 0.f;
    #pragma unroll
    for (int i = 0; i < 6; i++) {
        v[i] = *(const float4*)(xr + i * 128 + lane * 4);
        s  += v[i].x + v[i].y + v[i].z + v[i].w;
        s2 += v[i].x*v[i].x + v[i].y*v[i].y + v[i].z*v[i].z + v[i].w*v[i].w;
    }
    #pragma unroll
    for (int o = 16; o > 0; o >>= 1) {
        s  += __shfl_xor_sync(0xffffffffu, s,  o);
        s2 += __shfl_xor_sync(0xffffffffu, s2, o);
    }
    const float mu  = s * (1.0f / CDIM);
    const float var = s2 * (1.0f / CDIM) - mu * mu;
    const float inv = rsqrtf(var + 1e-6f);

    size_t ro = (size_t)row * CDIM;
    #pragma unroll
    for (int i = 0; i < 6; i++) {
        int c = i * 128 + lane * 4;
        float4 wv = *(const float4*)(w + c);
        float4 bv = *(const float4*)(b + c);
        float y0 = (v[i].x - mu) * inv * wv.x + bv.x;
        float y1 = (v[i].y - mu) * inv * wv.y + bv.y;
        float y2 = (v[i].z - mu) * inv * wv.z + bv.z;
        float y3 = (v[i].w - mu) * inv * wv.w + bv.w;
        uint32_t h01, l01, h23, l23;
        split_pack(y0, y1, h01, l01);
        split_pack(y2, y3, h23, l23);
        *(uint2*)(hi + ro + c) = make_uint2(h01, h23);
        *(uint2*)(lo + ro + c) = make_uint2(l01, l23);
    }
}

// ===========================================================================
// bf16-split tensor GEMM via ldmatrix + mma.sync.
// BK=32, double-buffered, 2 CTAs/SM (80 KB smem, <=128 regs).
// C[M,N] = A @ B^T ; A,B given as hi/lo bf16 [rows,K].
// 128x128 CTA tile, 256 threads (8 warps, each 64m x 32n).
// EPI 0: +bias -> fp32 ; EPI 1: (+bias)*lam+res -> fp32 ;
// EPI 2: gelu_exact(+bias) -> bf16 hi/lo ; EPI 3: +bias -> bf16 hi/lo
// ===========================================================================
#define RSB   80                        // bytes per smem row (64 + 16 pad)
#define TILEB (128 * RSB)               // 10240 bytes per tile
#define GEMM_SMEM (8 * TILEB)           // 2 stages x 4 tiles = 81920

template<int EPI>
__global__ __launch_bounds__(256, 2) void mmagemm(
    const __nv_bfloat16* __restrict__ Ahi, const __nv_bfloat16* __restrict__ Alo,
    const __nv_bfloat16* __restrict__ Bhi, const __nv_bfloat16* __restrict__ Blo,
    const float* __restrict__ bias,
    int M, int N, int K,
    float* __restrict__ Cf,
    __nv_bfloat16* __restrict__ Chi, __nv_bfloat16* __restrict__ Clo,
    const float* __restrict__ lam, const float* __restrict__ res)
{
    extern __shared__ char smc[];
    const uint32_t sb = smem_u32(smc);

    const int tid  = threadIdx.x;
    const int wid  = tid >> 5;
    const int lane = tid & 31;
    const int wm   = wid & 1;
    const int wn   = wid >> 1;
    const int m0   = blockIdx.y * 128;
    const int n0   = blockIdx.x * 128;

    // one tile: 128 rows x 32 bf16 (64B) ; 512 x 16B chunks / 256 thr = 2 each
    auto load_tile = [&](const __nv_bfloat16* __restrict__ G, int row0, int k0,
                         uint32_t dst) {
        #pragma unroll
        for (int i = 0; i < 2; i++) {
            int idx = tid + (i << 8);          // 0..511
            int r   = idx >> 2;
            int cc  = idx & 3;
            cp_async16(dst + r * RSB + cc * 16,
                       G + (size_t)(row0 + r) * K + k0 + cc * 8);
        }
    };
    auto load_chunk = [&](int k0, int p) {
        uint32_t base = sb + (uint32_t)p * (4 * TILEB);
        load_tile(Ahi, m0, k0, base);
        load_tile(Alo, m0, k0, base + TILEB);
        load_tile(Bhi, n0, k0, base + 2 * TILEB);
        load_tile(Blo, n0, k0, base + 3 * TILEB);
        CP_COMMIT();
    };

    float acc[4][4][4];
    #pragma unroll
    for (int t = 0; t < 4; t++)
        #pragma unroll
        for (int u = 0; u < 4; u++)
            #pragma unroll
            for (int e = 0; e < 4; e++) acc[t][u][e] = 0.f;

    const int nch = K >> 5;   // BK = 32 ; 24 or 96 chunks
    load_chunk(0, 0);
    load_chunk(32, 1);

    const int aRow = (lane & 7) + ((lane >> 3) & 1) * 8;
    const int aCol = (lane >> 4) * 16;
    const int bRow = (lane & 7) + (lane >> 4) * 8;
    const int bCol = ((lane >> 3) & 1) * 16;

    for (int it = 0; it < nch; ++it) {
        const int p = it & 1;
        if (it + 1 < nch) { CP_WAIT1(); } else { CP_WAIT0(); }
        __syncthreads();

        const uint32_t base = sb + (uint32_t)p * (4 * TILEB);
        const uint32_t sAh = base;
        const uint32_t sAl = base + TILEB;
        const uint32_t sBh = base + 2 * TILEB;
        const uint32_t sBl = base + 3 * TILEB;

        #pragma unroll
        for (int ks = 0; ks < 2; ks++) {
            const int kb = ks * 32;            // byte offset of k16 group
            uint32_t ah[4][4], al[4][4];
            #pragma unroll
            for (int t = 0; t < 4; t++) {
                uint32_t ro = (uint32_t)((wm * 64 + t * 16 + aRow) * RSB + kb + aCol);
                ldm_x4(ah[t], sAh + ro);
                ldm_x4(al[t], sAl + ro);
            }
            uint32_t bh[2][4];
            #pragma unroll
            for (int u2 = 0; u2 < 2; u2++) {
                uint32_t ro = (uint32_t)((wn * 32 + u2 * 16 + bRow) * RSB + kb + bCol);
                ldm_x4(bh[u2], sBh + ro);
            }
            #pragma unroll
            for (int t = 0; t < 4; t++)
                #pragma unroll
                for (int u = 0; u < 4; u++) {
                    mma_bf16(acc[t][u], ah[t], &bh[u >> 1][(u & 1) * 2]);
                    mma_bf16(acc[t][u], al[t], &bh[u >> 1][(u & 1) * 2]);
                }
            uint32_t bl[2][4];
            #pragma unroll
            for (int u2 = 0; u2 < 2; u2++) {
                uint32_t ro = (uint32_t)((wn * 32 + u2 * 16 + bRow) * RSB + kb + bCol);
                ldm_x4(bl[u2], sBl + ro);
            }
            #pragma unroll
            for (int t = 0; t < 4; t++)
                #pragma unroll
                for (int u = 0; u < 4; u++)
                    mma_bf16(acc[t][u], ah[t], &bl[u >> 1][(u & 1) * 2]);
        }
        __syncthreads();
        if (it + 2 < nch) load_chunk((it + 2) << 5, p);
    }

    #pragma unroll
    for (int t = 0; t < 4; t++) {
        const int rbase = m0 + wm * 64 + t * 16 + (lane >> 2);
        #pragma unroll
        for (int u = 0; u < 4; u++) {
            const int c = n0 + wn * 32 + u * 8 + (lane & 3) * 2;
            #pragma unroll
            for (int half = 0; half < 2; half++) {
                const int r = rbase + half * 8;
                const size_t ro = (size_t)r * N;
                float v0 = acc[t][u][half * 2 + 0] + bias[c];
                float v1 = acc[t][u][half * 2 + 1] + bias[c + 1];
                if (EPI == 1) {
                    v0 = v0 * lam[c]     + res[ro + c];
                    v1 = v1 * lam[c + 1] + res[ro + c + 1];
                    *(float2*)(Cf + ro + c) = make_float2(v0, v1);
                } else if (EPI == 2 || EPI == 3) {
                    if (EPI == 2) {
                        v0 = 0.5f * v0 * (1.0f + erff(v0 * 0.70710678118654752f));
                        v1 = 0.5f * v1 * (1.0f + erff(v1 * 0.70710678118654752f));
                    }
                    uint32_t hp, lp;
                    split_pack(v0, v1, hp, lp);
                    *(uint32_t*)(Chi + ro + c) = hp;
                    *(uint32_t*)(Clo + ro + c) = lp;
                } else {
                    *(float2*)(Cf + ro + c) = make_float2(v0, v1);
                }
            }
        }
    }
}

// ===========================================================================
// Flash attention on tensor cores (bf16-split, online softmax).
// Grid: (S/64, H, B), 128 threads (4 warps x m16 q-rows). BN = 64 keys/iter.
// ===========================================================================
#define ARS     144                      // attention smem row stride (bytes)
#define AT_Q    0
#define AT_BUF  18432
#define AT_TILE 9216
#define ATT_SMEM (18432 + 2 * 4 * 9216)  // 92160

__global__ __launch_bounds__(128) void attn_mma(
    const __nv_bfloat16* __restrict__ qhi, const __nv_bfloat16* __restrict__ qlo,
    __nv_bfloat16* __restrict__ chi, __nv_bfloat16* __restrict__ clo)
{
    extern __shared__ char smc[];
    const uint32_t sb = smem_u32(smc);
    const int tid  = threadIdx.x;
    const int wid  = tid >> 5;
    const int lane = tid & 31;
    const int h    = blockIdx.y;
    const int b    = blockIdx.z;
    const int q0   = blockIdx.x * 64;

    for (int i = tid; i < 512; i += 128) {
        int r = i >> 3, c = i & 7;
        size_t g = (size_t)(b * SS + q0 + r) * QKVC + h * DD + c * 8;
        cp_async16(sb + AT_Q + r * ARS + c * 16, qhi + g);
        cp_async16(sb + AT_Q + AT_TILE + r * ARS + c * 16, qlo + g);
    }
    CP_COMMIT();

    auto load_kv = [&](int j0, int p) {
        uint32_t base = sb + AT_BUF + (uint32_t)p * (4 * AT_TILE);
        for (int i = tid; i < 512; i += 128) {
            int r = i >> 3, c = i & 7;
            size_t gk = (size_t)(b * SS + j0 + r) * QKVC + CDIM + h * DD + c * 8;
            size_t gv = gk + CDIM;
            cp_async16(base + r * ARS + c * 16,                qhi + gk);
            cp_async16(base + AT_TILE + r * ARS + c * 16,      qlo + gk);
            cp_async16(base + 2 * AT_TILE + r * ARS + c * 16,  qhi + gv);
            cp_async16(base + 3 * AT_TILE + r * ARS + c * 16,  qlo + gv);
        }
        CP_COMMIT();
    };
    load_kv(0, 0);
    load_kv(64, 1);

    const int aRow = (lane & 7) + ((lane >> 3) & 1) * 8;
    const int aCol = (lane >> 4) * 16;
    const int bRow = (lane & 7) + (lane >> 4) * 8;
    const int bCol = ((lane >> 3) & 1) * 16;
    const int vRow = (lane & 7) + ((lane >> 3) & 1) * 8;
    const int vCol = (lane >> 4) * 16;

    CP_WAIT2();
    __syncthreads();

    uint32_t qh[4][4], ql[4][4];
    #pragma unroll
    for (int ks = 0; ks < 4; ks++) {
        uint32_t ro = (uint32_t)((wid * 16 + aRow) * ARS + ks * 32 + aCol);
        ldm_x4(qh[ks], sb + AT_Q + ro);
        ldm_x4(ql[ks], sb + AT_Q + AT_TILE + ro);
    }

    float oacc[8][4];
    #pragma unroll
    for (int u = 0; u < 8; u++)
        #pragma unroll
        for (int e = 0; e < 4; e++) oacc[u][e] = 0.f;
    float m0 = -1e30f, m1 = -1e30f, l0 = 0.f, l1 = 0.f;

    const int nt = SS / 64;
    for (int it = 0; it < nt; ++it) {
        const int p = it & 1;
        if (it + 1 < nt) { CP_WAIT1(); } else { CP_WAIT0(); }
        __syncthreads();

        const uint32_t base = sb + AT_BUF + (uint32_t)p * (4 * AT_TILE);
        const uint32_t sKh = base;
        const uint32_t sKl = base + AT_TILE;
        const uint32_t sVh = base + 2 * AT_TILE;
        const uint32_t sVl = base + 3 * AT_TILE;

        float sacc[8][4];
        #pragma unroll
        for (int u = 0; u < 8; u++)
            #pragma unroll
            for (int e = 0; e < 4; e++) sacc[u][e] = 0.f;

        #pragma unroll
        for (int ks = 0; ks < 4; ks++) {
            const int kb = ks * 32;
            uint32_t kh[4][4], kl[4][4];
            #pragma unroll
            for (int g = 0; g < 4; g++) {
                uint32_t ro = (uint32_t)((g * 16 + bRow) * ARS + kb + bCol);
                ldm_x4(kh[g], sKh + ro);
                ldm_x4(kl[g], sKl + ro);
            }
            #pragma unroll
            for (int g = 0; g < 4; g++)
                #pragma unroll
                for (int hf = 0; hf < 2; hf++) {
                    int u = g * 2 + hf;
                    mma_bf16(sacc[u], qh[ks], &kh[g][hf * 2]);
                    mma_bf16(sacc[u], ql[ks], &kh[g][hf * 2]);
                    mma_bf16(sacc[u], qh[ks], &kl[g][hf * 2]);
                }
        }

        float mx0 = m0, mx1 = m1;
        #pragma unroll
        for (int u = 0; u < 8; u++) {
            sacc[u][0] *= 0.125f; sacc[u][1] *= 0.125f;
            sacc[u][2] *= 0.125f; sacc[u][3] *= 0.125f;
            mx0 = fmaxf(mx0, fmaxf(sacc[u][0], sacc[u][1]));
            mx1 = fmaxf(mx1, fmaxf(sacc[u][2], sacc[u][3]));
        }
        mx0 = fmaxf(mx0, __shfl_xor_sync(0xffffffffu, mx0, 1));
        mx0 = fmaxf(mx0, __shfl_xor_sync(0xffffffffu, mx0, 2));
        mx1 = fmaxf(mx1, __shfl_xor_sync(0xffffffffu, mx1, 1));
        mx1 = fmaxf(mx1, __shfl_xor_sync(0xffffffffu, mx1, 2));
        float al0 = __expf(m0 - mx0), al1 = __expf(m1 - mx1);
        m0 = mx0; m1 = mx1;
        float sum0 = 0.f, sum1 = 0.f;
        #pragma unroll
        for (int u = 0; u < 8; u++) {
            sacc[u][0] = __expf(sacc[u][0] - m0);
            sacc[u][1] = __expf(sacc[u][1] - m0);
            sacc[u][2] = __expf(sacc[u][2] - m1);
            sacc[u][3] = __expf(sacc[u][3] - m1);
            sum0 += sacc[u][0] + sacc[u][1];
            sum1 += sacc[u][2] + sacc[u][3];
        }
        sum0 += __shfl_xor_sync(0xffffffffu, sum0, 1);
        sum0 += __shfl_xor_sync(0xffffffffu, sum0, 2);
        sum1 += __shfl_xor_sync(0xffffffffu, sum1, 1);
        sum1 += __shfl_xor_sync(0xffffffffu, sum1, 2);
        l0 = l0 * al0 + sum0;
        l1 = l1 * al1 + sum1;
        #pragma unroll
        for (int u = 0; u < 8; u++) {
            oacc[u][0] *= al0; oacc[u][1] *= al0;
            oacc[u][2] *= al1; oacc[u][3] *= al1;
        }

        uint32_t ph[4][4], pl[4][4];
        #pragma unroll
        for (int t = 0; t < 4; t++) {
            split_pack(sacc[2*t][0],   sacc[2*t][1],   ph[t][0], pl[t][0]);
            split_pack(sacc[2*t][2],   sacc[2*t][3],   ph[t][1], pl[t][1]);
            split_pack(sacc[2*t+1][0], sacc[2*t+1][1], ph[t][2], pl[t][2]);
            split_pack(sacc[2*t+1][2], sacc[2*t+1][3], ph[t][3], pl[t][3]);
        }

        #pragma unroll
        for (int t = 0; t < 4; t++) {
            uint32_t vh[4][4], vl[4][4];
            #pragma unroll
            for (int g = 0; g < 4; g++) {
                uint32_t ro = (uint32_t)((t * 16 + vRow) * ARS + g * 32 + vCol);
                ldm_x4t(vh[g], sVh + ro);
                ldm_x4t(vl[g], sVl + ro);
            }
            #pragma unroll
            for (int g = 0; g < 4; g++)
                #pragma unroll
                for (int hf = 0; hf < 2; hf++) {
                    int u = g * 2 + hf;
                    mma_bf16(oacc[u], ph[t], &vh[g][hf * 2]);
                    mma_bf16(oacc[u], pl[t], &vh[g][hf * 2]);
                    mma_bf16(oacc[u], ph[t], &vl[g][hf * 2]);
                }
        }

        __syncthreads();
        if (it + 2 < nt) load_kv((it + 2) * 64, p);
    }

    float inv0 = 1.0f / l0, inv1 = 1.0f / l1;
    const int r  = lane >> 2;
    const int cc = (lane & 3) * 2;
    #pragma unroll
    for (int u = 0; u < 8; u++) {
        int col = h * DD + u * 8 + cc;
        size_t o0 = (size_t)(b * SS + q0 + wid * 16 + r)     * CDIM + col;
        size_t o1 = (size_t)(b * SS + q0 + wid * 16 + r + 8) * CDIM + col;
        uint32_t hp, lp;
        split_pack(oacc[u][0] * inv0, oacc[u][1] * inv0, hp, lp);
        *(uint32_t*)(chi + o0) = hp;
        *(uint32_t*)(clo + o0) = lp;
        split_pack(oacc[u][2] * inv1, oacc[u][3] * inv1, hp, lp);
        *(uint32_t*)(chi + o1) = hp;
        *(uint32_t*)(clo + o1) = lp;
    }
}

// ===========================================================================
// Launch
// ===========================================================================
extern "C" void kernel_launch(void* const* d_in, const int* in_sizes, int n_in,
                              void* d_out, int out_size)
{
    const float* hs    = (const float*)d_in[0];
    const float* ln1_w = (const float*)d_in[1];
    const float* ln1_b = (const float*)d_in[2];
    const float* q_w   = (const float*)d_in[3];
    const float* q_b   = (const float*)d_in[4];
    const float* k_w   = (const float*)d_in[5];
    const float* k_b   = (const float*)d_in[6];
    const float* v_w   = (const float*)d_in[7];
    const float* v_b   = (const float*)d_in[8];
    const float* o_w   = (const float*)d_in[9];
    const float* o_b   = (const float*)d_in[10];
    const float* lam1  = (const float*)d_in[11];
    const float* ln2_w = (const float*)d_in[12];
    const float* ln2_b = (const float*)d_in[13];
    const float* fc1_w = (const float*)d_in[14];
    const float* fc1_b = (const float*)d_in[15];
    const float* fc2_w = (const float*)d_in[16];
    const float* fc2_b = (const float*)d_in[17];
    const float* lam2  = (const float*)d_in[18];
    float* out = (float*)d_out;

    __nv_bfloat16 *wqkv_hi, *wqkv_lo, *wo_hi, *wo_lo, *wf1_hi, *wf1_lo, *wf2_hi, *wf2_lo;
    __nv_bfloat16 *xn_hi, *xn_lo, *qkv_hi, *qkv_lo, *ctx_hi, *ctx_lo, *y2_hi, *y2_lo, *h1_hi, *h1_lo;
    float *qkvb, *hid;
    cudaGetSymbolAddress((void**)&wqkv_hi, g_wqkv_hi);
    cudaGetSymbolAddress((void**)&wqkv_lo, g_wqkv_lo);
    cudaGetSymbolAddress((void**)&wo_hi,   g_wo_hi);
    cudaGetSymbolAddress((void**)&wo_lo,   g_wo_lo);
    cudaGetSymbolAddress((void**)&wf1_hi,  g_wf1_hi);
    cudaGetSymbolAddress((void**)&wf1_lo,  g_wf1_lo);
    cudaGetSymbolAddress((void**)&wf2_hi,  g_wf2_hi);
    cudaGetSymbolAddress((void**)&wf2_lo,  g_wf2_lo);
    cudaGetSymbolAddress((void**)&qkvb,    g_qkvb);
    cudaGetSymbolAddress((void**)&xn_hi,   g_xn_hi);
    cudaGetSymbolAddress((void**)&xn_lo,   g_xn_lo);
    cudaGetSymbolAddress((void**)&qkv_hi,  g_qkv_hi);
    cudaGetSymbolAddress((void**)&qkv_lo,  g_qkv_lo);
    cudaGetSymbolAddress((void**)&ctx_hi,  g_ctx_hi);
    cudaGetSymbolAddress((void**)&ctx_lo,  g_ctx_lo);
    cudaGetSymbolAddress((void**)&hid,     g_hid);
    cudaGetSymbolAddress((void**)&y2_hi,   g_y2_hi);
    cudaGetSymbolAddress((void**)&y2_lo,   g_y2_lo);
    cudaGetSymbolAddress((void**)&h1_hi,   g_h1_hi);
    cudaGetSymbolAddress((void**)&h1_lo,   g_h1_lo);

    // 1) weight prep + bias concat
    wsplit_all<<<WS_BLOCKS, 256>>>(q_w, k_w, v_w, o_w, fc1_w, fc2_w,
                                   wqkv_hi, wqkv_lo, wo_hi, wo_lo,
                                   wf1_hi, wf1_lo, wf2_hi, wf2_lo);
    catbias<<<9, 256>>>(q_b, k_b, v_b, qkvb);

    cudaFuncSetAttribute(mmagemm<0>, cudaFuncAttributeMaxDynamicSharedMemorySize, GEMM_SMEM);
    cudaFuncSetAttribute(mmagemm<1>, cudaFuncAttributeMaxDynamicSharedMemorySize, GEMM_SMEM);
    cudaFuncSetAttribute(mmagemm<2>, cudaFuncAttributeMaxDynamicSharedMemorySize, GEMM_SMEM);
    cudaFuncSetAttribute(mmagemm<3>, cudaFuncAttributeMaxDynamicSharedMemorySize, GEMM_SMEM);
    cudaFuncSetAttribute(attn_mma,   cudaFuncAttributeMaxDynamicSharedMemorySize, ATT_SMEM);

    // 2) LN1 -> bf16 split
    ln_split<<<TOK / 8, 256>>>(hs, ln1_w, ln1_b, xn_hi, xn_lo);

    // 3) fused QKV -> bf16 hi/lo
    mmagemm<3><<<dim3(QKVC / 128, TOK / 128), 256, GEMM_SMEM>>>(
        xn_hi, xn_lo, wqkv_hi, wqkv_lo, qkvb, TOK, QKVC, CDIM,
        nullptr, qkv_hi, qkv_lo, nullptr, nullptr);

    // 4) attention -> ctx hi/lo
    attn_mma<<<dim3(SS / 64, HH, BB), 128, ATT_SMEM>>>(qkv_hi, qkv_lo, ctx_hi, ctx_lo);

    // 5) O projection + lam1*. + shortcut -> hid fp32   [ncu captures this]
    mmagemm<1><<<dim3(CDIM / 128, TOK / 128), 256, GEMM_SMEM>>>(
        ctx_hi, ctx_lo, wo_hi, wo_lo, o_b, TOK, CDIM, CDIM,
        hid, nullptr, nullptr, lam1, hs);

    // 6) LN2 -> bf16 split
    ln_split<<<TOK / 8, 256>>>(hid, ln2_w, ln2_b, y2_hi, y2_lo);

    // 7) FC1 + exact GELU -> h1 hi/lo
    mmagemm<2><<<dim3(FDIM / 128, TOK / 128), 256, GEMM_SMEM>>>(
        y2_hi, y2_lo, wf1_hi, wf1_lo, fc1_b, TOK, FDIM, CDIM,
        nullptr, h1_hi, h1_lo, nullptr, nullptr);

    // 8) FC2 + lam2*. + hid -> out fp32
    mmagemm<1><<<dim3(CDIM / 128, TOK / 128), 256, GEMM_SMEM>>>(
        h1_hi, h1_lo, wf2_hi, wf2_lo, fc2_b, TOK, CDIM, FDIM,
        out, nullptr, nullptr, lam2, hid);
}